// round 12
// baseline (speedup 1.0000x reference)
#include <cuda_runtime.h>
#include <math.h>
#include <stdint.h>

// ===========================================================================
// img_attention via warp-level TF32 mma.sync (compute_103-safe)
//   c_img = softmax(v . tanh(Wh g* + Ws s + Wc cov)) @ g*
//   g*    = X @ (W_g @ W_gs) + (b_g @ W_gs + b_gs)      [algebraic fold]
// GEMMs: D[m,n] = sum_k A[m,k] * Bt[n,k]  (both K-major)
// R11: fragment double-buffering — ldsm for kc+1 overlaps MMAs of kc,
//      hiding shared-mem latency that held tensor pipe at ~61%.
// ===========================================================================

#define B_   128
#define N_   49
#define G_   4096
#define H_   1024
#define A_   1024
#define BN_  (B_ * N_)   // 6272

__device__ float g_WcombT[H_ * G_];       // [1024,4096] (rounded)
__device__ float g_biascomb[H_];
__device__ float g_gstar[BN_ * H_];       // [6272,1024] raw fp32
__device__ float g_parts[3 * BN_ * H_];   // split-K partial buffers
__device__ float g_WgsT[H_ * G_];         // W_gs^T rounded [1024,4096]
__device__ float g_WhT[A_ * H_];          // rounded
__device__ float g_WsT[A_ * H_];          // rounded
__device__ float g_str[B_ * H_];          // s_t rounded
__device__ float g_sproj[B_ * A_];
__device__ float g_scores[BN_];

// ---------------------------------------------------------------------------
__device__ __forceinline__ uint32_t smem_u32(const void* p) {
    uint32_t a;
    asm("{ .reg .u64 t; cvta.to.shared.u64 t, %1; cvt.u32.u64 %0, t; }"
        : "=r"(a) : "l"(p));
    return a;
}
__device__ __forceinline__ float to_tf32(float x) {
    uint32_t u;
    asm("cvt.rna.tf32.f32 %0, %1;" : "=r"(u) : "f"(x));
    return __uint_as_float(u);
}
__device__ __forceinline__ uint32_t to_tf32_u(uint32_t x) {
    uint32_t u;
    asm("cvt.rna.tf32.f32 %0, %1;" : "=r"(u) : "f"(__uint_as_float(x)));
    return u;
}
__device__ __forceinline__ float tanh_approx(float x) {
    float y;
    asm("tanh.approx.f32 %0, %1;" : "=f"(y) : "f"(x));
    return y;
}
__device__ __forceinline__ void ldsm4(uint32_t* r, uint32_t addr) {
    asm volatile("ldmatrix.sync.aligned.m8n8.x4.shared.b16 {%0,%1,%2,%3}, [%4];"
                 : "=r"(r[0]), "=r"(r[1]), "=r"(r[2]), "=r"(r[3]) : "r"(addr));
}
__device__ __forceinline__ void mma_tf32(float* d, const uint32_t* a,
                                         const uint32_t* b) {
    asm volatile(
        "mma.sync.aligned.m16n8k8.row.col.f32.tf32.tf32.f32 "
        "{%0,%1,%2,%3}, {%4,%5,%6,%7}, {%8,%9}, {%0,%1,%2,%3};"
        : "+f"(d[0]), "+f"(d[1]), "+f"(d[2]), "+f"(d[3])
        : "r"(a[0]), "r"(a[1]), "r"(a[2]), "r"(a[3]), "r"(b[0]), "r"(b[1]));
}
#define CPA(dst, src) \
    asm volatile("cp.async.cg.shared.global [%0], [%1], 16;" \
                 :: "r"(dst), "l"(src) : "memory")
#define CPCOMMIT() asm volatile("cp.async.commit_group;" ::: "memory")
#define CPWAIT1()  asm volatile("cp.async.wait_group 1;" ::: "memory")
#define CPWAIT0()  asm volatile("cp.async.wait_group 0;" ::: "memory")

// ---------------------------------------------------------------------------
// Templated GEMM core. FM = A-fragments per warp (M-tile = FM*32).
//   FM=4: block 128x128, 2 CTAs/SM (96KB smem)
//   FM=2: block  64x128, 3 CTAs/SM (72KB smem)
// 2x2 warps; warp tile (FM*16)x64. BK=32. 3-stage cp.async ring.
// Fragment double-buffer: ldsm(kc+1) issues before MMA(kc) wave.
// ---------------------------------------------------------------------------
template <int FM>
struct GemmDims {
    static const int ABYTES = FM * 32 * 128;
    static const int STAGE  = ABYTES + 16384;
    static const int SMEM   = 3 * STAGE;
    static const int OCC    = (FM == 2) ? 3 : 2;
};

#define GEMM_PROLOG(FM)                                                       \
    extern __shared__ char smem[];                                            \
    const uint32_t sb = smem_u32(smem);                                       \
    const int tid = threadIdx.x;                                              \
    const int lane = tid & 31;                                                \
    const int wid = tid >> 5;                                                 \
    const int wr = wid >> 1;   /* 0..1 */                                     \
    const int wc = wid & 1;    /* 0..1 */                                     \
    const int srow = tid >> 3, sc4 = tid & 7;                                 \
    const uint32_t soff0 = (uint32_t)srow * 128 + ((sc4 ^ (srow & 7)) << 4);  \
    const int aRow = wr * (FM * 16) + ((lane >> 3) & 1) * 8 + (lane & 7);     \
    const int cbA = lane >> 4;                                                \
    const uint32_t aBase = (uint32_t)aRow * 128;                              \
    const int rmA = aRow & 7;                                                 \
    const int bRow = wc * 64 + (lane >> 4) * 8 + (lane & 7);                  \
    const int cbB = (lane >> 3) & 1;                                          \
    const uint32_t bBase = (uint32_t)bRow * 128;                              \
    const int rmB = bRow & 7;                                                 \
    float acc[FM][8][4];                                                      \
    _Pragma("unroll") for (int i = 0; i < FM; i++)                            \
        _Pragma("unroll") for (int j = 0; j < 8; j++)                         \
            _Pragma("unroll") for (int q = 0; q < 4; q++) acc[i][j][q] = 0.f;

template <int FM, int CVTA, int CVTB>
__device__ __forceinline__ void gemm_core(
    const float* __restrict__ pA0, const float* __restrict__ pB0,
    size_t strideJ, int nch, uint32_t sb, uint32_t soff0,
    uint32_t aBase, int rmA, int cbA,
    uint32_t bBase, int rmB, int cbB,
    float (&acc)[FM][8][4])
{
    const int ABYTES = GemmDims<FM>::ABYTES;
    const int STAGE  = GemmDims<FM>::STAGE;
    const int JA = FM * 2;

    auto issue = [&](uint32_t sbase, int k0) {
        #pragma unroll
        for (int j = 0; j < JA; j++)
            CPA(sbase + soff0 + j * 2048, pA0 + k0 + j * strideJ);
        #pragma unroll
        for (int j = 0; j < 8; j++)
            CPA(sbase + ABYTES + soff0 + j * 2048, pB0 + k0 + j * strideJ);
        CPCOMMIT();
    };

    uint32_t afr[2][FM][4], bfr[2][8][2];

    auto ldA = [&](uint32_t As, int kc, int buf) {
        #pragma unroll
        for (int fm = 0; fm < FM; fm++) {
            ldsm4(afr[buf][fm],
                  As + fm * 2048 + aBase + ((((kc * 2) + cbA) ^ rmA) << 4));
            if (CVTA) {
                #pragma unroll
                for (int q = 0; q < 4; q++)
                    afr[buf][fm][q] = to_tf32_u(afr[buf][fm][q]);
            }
        }
    };
    auto ldB = [&](uint32_t Bs, int kc, int buf) {
        #pragma unroll
        for (int p = 0; p < 4; p++) {
            uint32_t t4[4];
            ldsm4(t4, Bs + p * 2048 + bBase + ((((kc * 2) + cbB) ^ rmB) << 4));
            if (CVTB) {
                #pragma unroll
                for (int q = 0; q < 4; q++)
                    t4[q] = to_tf32_u(t4[q]);
            }
            bfr[buf][2*p][0]   = t4[0]; bfr[buf][2*p][1]   = t4[1];
            bfr[buf][2*p+1][0] = t4[2]; bfr[buf][2*p+1][1] = t4[3];
        }
    };

    issue(sb, 0);
    issue(sb + STAGE, 32);
    int cs = 0, is = 2;
    for (int c = 0; c < nch; c++) {
        if (c == nch - 1) { CPWAIT0(); } else { CPWAIT1(); }
        __syncthreads();
        if (c + 2 < nch) {
            issue(sb + is * STAGE, (c + 2) * 32);
            is = (is == 2) ? 0 : is + 1;
        }
        const uint32_t As = sb + cs * STAGE;
        const uint32_t Bs = As + ABYTES;
        ldA(As, 0, 0);
        ldB(Bs, 0, 0);
        #pragma unroll
        for (int kc = 0; kc < 4; kc++) {
            const int cur = kc & 1;
            if (kc < 3) {           // prefetch next fragments under the MMAs
                ldA(As, kc + 1, cur ^ 1);
                ldB(Bs, kc + 1, cur ^ 1);
            }
            #pragma unroll
            for (int fm = 0; fm < FM; fm++)
                #pragma unroll
                for (int fn = 0; fn < 8; fn++)
                    mma_tf32(acc[fm][fn], afr[cur][fm], bfr[cur][fn]);
        }
        cs = (cs == 2) ? 0 : cs + 1;
    }
}

// ---------------------------------------------------------------------------
// Split-K partial GEMM: Cpart[z] = A @ Bt^T over K slice z (plain stores).
// ---------------------------------------------------------------------------
template <int FM, int CVTA, int CVTB>
__global__ __launch_bounds__(128, GemmDims<FM>::OCC)
void mma_gemm_part(const float* __restrict__ A, const float* __restrict__ Bt,
                   float* __restrict__ Cparts, size_t zstride,
                   int Nn, int K, int nchA)
{
    const int bm = blockIdx.y * (FM * 32);
    const int bn = blockIdx.x * 128;
    const int z  = blockIdx.z;
    const int kbase = z * nchA * 32;
    int nch = (K >> 5) - z * nchA;
    if (nch > nchA) nch = nchA;
    float* C = Cparts + (size_t)z * zstride;

    GEMM_PROLOG(FM);
    const float* pA0 = A  + (size_t)(bm + srow) * K + kbase + sc4 * 4;
    const float* pB0 = Bt + (size_t)(bn + srow) * K + kbase + sc4 * 4;
    const size_t strideJ = (size_t)16 * K;
    gemm_core<FM, CVTA, CVTB>(pA0, pB0, strideJ, nch, sb, soff0,
                              aBase, rmA, cbA, bBase, rmB, cbB, acc);

    const int gid = lane >> 2, tig = lane & 3;
    #pragma unroll
    for (int fm = 0; fm < FM; fm++) {
        const int row = bm + wr * (FM * 16) + fm * 16 + gid;
        #pragma unroll
        for (int fn = 0; fn < 8; fn++) {
            const int col = bn + wc * 64 + fn * 8 + tig * 2;
            float2 v01, v23;
            v01.x = acc[fm][fn][0]; v01.y = acc[fm][fn][1];
            v23.x = acc[fm][fn][2]; v23.y = acc[fm][fn][3];
            *(float2*)(C + (size_t)row * Nn + col) = v01;
            *(float2*)(C + (size_t)(row + 8) * Nn + col) = v23;
        }
    }
}

// ---------------------------------------------------------------------------
// Split-K GEMM for skinny M=128 (sproj): C += A @ Bt^T over K slice, atomics.
// ---------------------------------------------------------------------------
__global__ __launch_bounds__(128, 2)
void mma_gemm_splitk(const float* __restrict__ A, const float* __restrict__ Bt,
                     float* __restrict__ C, int M, int Nn, int K, int klen)
{
    const int bm = blockIdx.y * 128;
    const int bn = blockIdx.x * 128;
    const int kbase = blockIdx.z * klen;
    GEMM_PROLOG(4);
    const float* pA0 = A  + (size_t)(bm + srow) * K + kbase + sc4 * 4;
    const float* pB0 = Bt + (size_t)(bn + srow) * K + kbase + sc4 * 4;
    const size_t strideJ = (size_t)16 * K;
    gemm_core<4, 0, 0>(pA0, pB0, strideJ, klen >> 5, sb, soff0,
                       aBase, rmA, cbA, bBase, rmB, cbB, acc);

    const int gid = lane >> 2, tig = lane & 3;
    #pragma unroll
    for (int fm = 0; fm < 4; fm++) {
        const int row = bm + wr * 64 + fm * 16 + gid;
        #pragma unroll
        for (int fn = 0; fn < 8; fn++) {
            const int col = bn + wc * 64 + fn * 8 + tig * 2;
            atomicAdd(C + (size_t)row * Nn + col,       acc[fm][fn][0]);
            atomicAdd(C + (size_t)row * Nn + col + 1,   acc[fm][fn][1]);
            atomicAdd(C + (size_t)(row+8) * Nn + col,   acc[fm][fn][2]);
            atomicAdd(C + (size_t)(row+8) * Nn + col+1, acc[fm][fn][3]);
        }
    }
}

// ---------------------------------------------------------------------------
// Fused e_pre GEMM + scores epilogue (FM=2 tiles, 3 CTAs/SM).
// A = gstar (raw fp32 -> CVTA=1), B = WhT (pre-rounded).
// ---------------------------------------------------------------------------
__global__ __launch_bounds__(128, 3)
void epre_scores_gemm(const float* __restrict__ A, const float* __restrict__ Bt,
                      const float* __restrict__ sproj,
                      const float* __restrict__ cov,
                      const float* __restrict__ Wc,
                      const float* __restrict__ v,
                      float* __restrict__ scores)
{
    const int bm = blockIdx.y * 64;
    const int bn = blockIdx.x * 128;
    GEMM_PROLOG(2);
    const float* pA0 = A  + (size_t)(bm + srow) * H_ + sc4 * 4;
    const float* pB0 = Bt + (size_t)(bn + srow) * H_ + sc4 * 4;
    const size_t strideJ = (size_t)16 * H_;
    gemm_core<2, 1, 0>(pA0, pB0, strideJ, H_ >> 5, sb, soff0,
                       aBase, rmA, cbA, bBase, rmB, cbB, acc);

    const int gid = lane >> 2, tig = lane & 3;
    float vv[16], wcv[16];
    #pragma unroll
    for (int fn = 0; fn < 8; fn++) {
        const int col = bn + wc * 64 + fn * 8 + tig * 2;
        vv[2*fn]   = v[col];      vv[2*fn+1]  = v[col + 1];
        wcv[2*fn]  = Wc[col];     wcv[2*fn+1] = Wc[col + 1];
    }
    #pragma unroll
    for (int fm = 0; fm < 2; fm++) {
        const int r0 = bm + wr * 32 + fm * 16 + gid;
        const int r1 = r0 + 8;
        const int b0i = r0 / N_, b1i = r1 / N_;
        const float c0 = cov[r0], c1 = cov[r1];
        const float* sp0 = sproj + (size_t)b0i * A_;
        const float* sp1 = sproj + (size_t)b1i * A_;
        float p0 = 0.f, p1 = 0.f;
        #pragma unroll
        for (int fn = 0; fn < 8; fn++) {
            const int col = bn + wc * 64 + fn * 8 + tig * 2;
            p0 += vv[2*fn]   * tanh_approx(acc[fm][fn][0] + sp0[col]     + c0 * wcv[2*fn]);
            p0 += vv[2*fn+1] * tanh_approx(acc[fm][fn][1] + sp0[col + 1] + c0 * wcv[2*fn+1]);
            p1 += vv[2*fn]   * tanh_approx(acc[fm][fn][2] + sp1[col]     + c1 * wcv[2*fn]);
            p1 += vv[2*fn+1] * tanh_approx(acc[fm][fn][3] + sp1[col + 1] + c1 * wcv[2*fn+1]);
        }
        p0 += __shfl_xor_sync(0xffffffffu, p0, 1);
        p0 += __shfl_xor_sync(0xffffffffu, p0, 2);
        p1 += __shfl_xor_sync(0xffffffffu, p1, 1);
        p1 += __shfl_xor_sync(0xffffffffu, p1, 2);
        if (tig == 0) {
            atomicAdd(scores + r0, p0);
            atomicAdd(scores + r1, p1);
        }
    }
}

// ---------------------------------------------------------------------------
// Reductions over split-K partials.
// ---------------------------------------------------------------------------
__global__ __launch_bounds__(256) void reduce2_round_kernel(
    const float* __restrict__ p0, const float* __restrict__ p1,
    float* __restrict__ out)
{
    const size_t i = ((size_t)blockIdx.x * 256 + threadIdx.x) * 4;
    float4 a = *(const float4*)(p0 + i);
    float4 b = *(const float4*)(p1 + i);
    float4 r;
    r.x = to_tf32(a.x + b.x); r.y = to_tf32(a.y + b.y);
    r.z = to_tf32(a.z + b.z); r.w = to_tf32(a.w + b.w);
    *(float4*)(out + i) = r;
}

__global__ __launch_bounds__(256) void reduce3_bias_kernel(
    const float* __restrict__ p0, const float* __restrict__ p1,
    const float* __restrict__ p2, const float* __restrict__ bias,
    float* __restrict__ out)
{
    const size_t idx = (size_t)blockIdx.x * 256 + threadIdx.x;
    const size_t i = idx * 4;
    const int col = (int)(i & (H_ - 1));
    float4 a = *(const float4*)(p0 + i);
    float4 b = *(const float4*)(p1 + i);
    float4 c = *(const float4*)(p2 + i);
    float4 d = *(const float4*)(bias + col);
    float4 r;
    r.x = a.x + b.x + c.x + d.x;
    r.y = a.y + b.y + c.y + d.y;
    r.z = a.z + b.z + c.z + d.z;
    r.w = a.w + b.w + c.w + d.w;
    *(float4*)(out + i) = r;
}

// ---------------------------------------------------------------------------
// Batched prologue: rounded transposes, zero-fills, s_t rounding, bias init.
// ---------------------------------------------------------------------------
#define PREP_T1 4096
#define PREP_T2 (PREP_T1 + 1024)
#define PREP_T3 (PREP_T2 + 1024)
#define PREP_ZS (PREP_T3 + 25)
#define PREP_ZP (PREP_ZS + 512)
#define PREP_RS (PREP_ZP + 128)
#define PREP_BI (PREP_RS + 4)
#define PREP_END PREP_BI

__device__ __forceinline__ void do_transpose32r(
    const float* __restrict__ in, float* __restrict__ out,
    int R, int C, int tx, int ty)
{
    __shared__ float t[32][33];
    const int c0 = tx * 32, r0 = ty * 32;
    const int x = threadIdx.x & 31, y = (threadIdx.x >> 5);
    #pragma unroll
    for (int j = 0; j < 32; j += 8)
        t[y + j][x] = in[(size_t)(r0 + y + j) * C + c0 + x];
    __syncthreads();
    #pragma unroll
    for (int j = 0; j < 32; j += 8)
        out[(size_t)(c0 + y + j) * R + r0 + x] = to_tf32(t[x][y + j]);
}

__global__ __launch_bounds__(256) void prep_kernel(
    const float* __restrict__ W_gs, float* __restrict__ WgsT,
    const float* __restrict__ W_h,  float* __restrict__ WhT,
    const float* __restrict__ W_s,  float* __restrict__ WsT,
    const float* __restrict__ s_t,  float* __restrict__ str,
    const float* __restrict__ b_gs, float* __restrict__ biascomb,
    float* __restrict__ scores, float* __restrict__ sproj)
{
    const int bid = blockIdx.x;
    if (bid < PREP_T1) {
        do_transpose32r(W_gs, WgsT, G_, H_, bid & 31, bid >> 5);
    } else if (bid < PREP_T2) {
        const int b = bid - PREP_T1;
        do_transpose32r(W_h, WhT, H_, A_, b & 31, b >> 5);
    } else if (bid < PREP_T3) {
        const int b = bid - PREP_T2;
        do_transpose32r(W_s, WsT, H_, A_, b & 31, b >> 5);
    } else if (bid < PREP_ZS) {
        const int i = (bid - PREP_T3) * 256 + threadIdx.x;
        if (i < BN_) scores[i] = 0.f;
    } else if (bid < PREP_ZP) {
        const int i = (bid - PREP_ZS) * 256 + threadIdx.x;
        sproj[i] = 0.f;
    } else if (bid < PREP_RS) {
        const int i = (bid - PREP_ZP) * 256 + threadIdx.x;
        float4 x = *(const float4*)(s_t + (size_t)i * 4);
        x.x = to_tf32(x.x); x.y = to_tf32(x.y);
        x.z = to_tf32(x.z); x.w = to_tf32(x.w);
        *(float4*)(str + (size_t)i * 4) = x;
    } else {
        const int h = (bid - PREP_RS) * 256 + threadIdx.x;
        biascomb[h] = b_gs[h];
    }
}

__global__ void bias_acc_kernel(const float* __restrict__ b_g,
                                const float* __restrict__ W_gs,
                                float* __restrict__ bias) {
    int h = blockIdx.x * blockDim.x + threadIdx.x;
    int k0 = blockIdx.y * 256;
    float acc = 0.f;
    #pragma unroll 4
    for (int k = k0; k < k0 + 256; k++)
        acc += b_g[k] * W_gs[(size_t)k * H_ + h];
    atomicAdd(&bias[h], acc);
}

// softmax over N=49 + context c[b,h] = sum_n alpha[n] * gstar[b,n,h]
__global__ __launch_bounds__(256) void context_kernel(
    const float* __restrict__ scores, const float* __restrict__ gstar,
    float* __restrict__ out)
{
    const int b = blockIdx.x;
    __shared__ float alpha[N_];
    const int tid = threadIdx.x;

    if (tid == 0) {
        float m = -1e30f;
        #pragma unroll
        for (int n = 0; n < N_; n++) m = fmaxf(m, scores[b * N_ + n]);
        float s = 0.f;
        #pragma unroll
        for (int n = 0; n < N_; n++) {
            float e = expf(scores[b * N_ + n] - m);
            alpha[n] = e;
            s += e;
        }
        float inv = 1.f / s;
        #pragma unroll
        for (int n = 0; n < N_; n++) alpha[n] *= inv;
    }
    __syncthreads();

    const float* gb = gstar + (size_t)b * N_ * H_;
    for (int h = tid; h < H_; h += 256) {
        float acc = 0.f;
        #pragma unroll
        for (int n = 0; n < N_; n++)
            acc += alpha[n] * gb[(size_t)n * H_ + h];
        out[(size_t)b * H_ + h] = acc;
    }
}

// ---------------------------------------------------------------------------
extern "C" void kernel_launch(void* const* d_in, const int* in_sizes, int n_in,
                              void* d_out, int out_size) {
    const float* X    = (const float*)d_in[0];   // [6272,4096]
    const float* s_t  = (const float*)d_in[1];   // [128,1024]
    const float* cov  = (const float*)d_in[2];   // [6272]
    const float* W_g  = (const float*)d_in[3];   // [4096,4096]
    const float* b_g  = (const float*)d_in[4];   // [4096]
    const float* W_gs = (const float*)d_in[5];   // [4096,1024]
    const float* b_gs = (const float*)d_in[6];   // [1024]
    const float* W_h  = (const float*)d_in[7];   // [1024,1024]
    const float* W_s  = (const float*)d_in[8];   // [1024,1024]
    const float* W_c  = (const float*)d_in[9];   // [1024]
    const float* v    = (const float*)d_in[10];  // [1024]
    float* out = (float*)d_out;                  // [128,1024]

    float *WcombT, *biascomb, *gstar, *parts, *WgsT, *WhT, *WsT;
    float *str, *sproj, *scores;
    cudaGetSymbolAddress((void**)&WcombT,   g_WcombT);
    cudaGetSymbolAddress((void**)&biascomb, g_biascomb);
    cudaGetSymbolAddress((void**)&gstar,    g_gstar);
    cudaGetSymbolAddress((void**)&parts,    g_parts);
    cudaGetSymbolAddress((void**)&WgsT,     g_WgsT);
    cudaGetSymbolAddress((void**)&WhT,      g_WhT);
    cudaGetSymbolAddress((void**)&WsT,      g_WsT);
    cudaGetSymbolAddress((void**)&str,      g_str);
    cudaGetSymbolAddress((void**)&sproj,    g_sproj);
    cudaGetSymbolAddress((void**)&scores,   g_scores);

    const int SM4 = GemmDims<4>::SMEM;   // 96KB
    const int SM2 = GemmDims<2>::SMEM;   // 72KB
    cudaFuncSetAttribute(mma_gemm_part<4, 0, 1>,
                         cudaFuncAttributeMaxDynamicSharedMemorySize, SM4);
    cudaFuncSetAttribute(mma_gemm_part<4, 1, 0>,
                         cudaFuncAttributeMaxDynamicSharedMemorySize, SM4);
    cudaFuncSetAttribute(mma_gemm_splitk,
                         cudaFuncAttributeMaxDynamicSharedMemorySize, SM4);
    cudaFuncSetAttribute(epre_scores_gemm,
                         cudaFuncAttributeMaxDynamicSharedMemorySize, SM2);

    // prologue: rounded transposes, zero-fills, s_t rounding, bias init
    prep_kernel<<<PREP_END, 256>>>(W_gs, WgsT, W_h, WhT, W_s, WsT,
                                   s_t, str, b_gs, biascomb, scores, sproj);
    bias_acc_kernel<<<dim3(H_ / 256, G_ / 256), 256>>>(b_g, W_gs, biascomb);

    // WcombT = WgsT @ W_g^T, split-K x2 (64+64 chunks), reduce+round
    mma_gemm_part<4, 0, 1><<<dim3(G_ / 128, H_ / 128, 2), 128, SM4>>>(
        WgsT, W_g, parts, (size_t)H_ * G_, G_, G_, 64);
    reduce2_round_kernel<<<(H_ * G_ / 4) / 256, 256>>>(
        parts, parts + (size_t)H_ * G_, WcombT);

    // gstar partials = X @ WcombT^T, split-K x3 (43/43/42 chunks)
    mma_gemm_part<4, 1, 0><<<dim3(H_ / 128, BN_ / 128, 3), 128, SM4>>>(
        X, WcombT, parts, (size_t)BN_ * H_, H_, G_, 43);
    // gstar = p0+p1+p2 + biascomb
    reduce3_bias_kernel<<<(BN_ * H_ / 4) / 256, 256>>>(
        parts, parts + (size_t)BN_ * H_, parts + 2 * (size_t)BN_ * H_,
        biascomb, gstar);

    // s_proj = str @ WsT^T   (split-K x8, atomic)
    mma_gemm_splitk<<<dim3(A_ / 128, 1, 8), 128, SM4>>>(
        str, WsT, sproj, B_, A_, H_, H_ / 8);

    // fused: e_pre + tanh + v-dot -> scores
    epre_scores_gemm<<<dim3(A_ / 128, BN_ / 64), 128, SM2>>>(
        gstar, WhT, sproj, cov, W_c, v, scores);

    context_kernel<<<B_, 256>>>(scores, gstar, out);
}

// round 14
// speedup vs baseline: 1.4907x; 1.4907x over previous
#include <cuda_runtime.h>
#include <cuda_fp16.h>
#include <math.h>
#include <stdint.h>

// ===========================================================================
// img_attention via warp-level FP16 mma.sync m16n8k16 (compute_103-safe)
//   c_img = softmax(v . tanh(Wh g* + Ws s + Wc cov)) @ g*
//   g*    = X @ (W_g @ W_gs) + (b_g @ W_gs + b_gs)      [algebraic fold]
// GEMMs: D[m,n] = sum_k A[m,k] * Bt[n,k]  (both K-major, fp16 operands,
// fp32 accumulate). fp16 mantissa == TF32 mantissa (10 bits) but 2x rate.
// R13: R12 with the nonexistent __half2_as_ushort2 intrinsic replaced by
//      direct __half2 stores (compile fix only).
// ===========================================================================

#define B_   128
#define N_   49
#define G_   4096
#define H_   1024
#define A_   1024
#define BN_  (B_ * N_)   // 6272

__device__ __half g_Xh[BN_ * G_];        // X fp16 [6272,4096]
__device__ __half g_Wgh[G_ * G_];        // W_g fp16 [4096,4096]
__device__ __half g_WgsTh[H_ * G_];      // W_gs^T fp16 [1024,4096]
__device__ __half g_WcombTh[H_ * G_];    // (W_g@W_gs)^T fp16
__device__ __half g_WhTh[A_ * H_];       // W_h^T fp16
__device__ __half g_WsTh[A_ * H_];       // W_s^T fp16
__device__ __half g_sth[B_ * H_];        // s_t fp16
__device__ __half g_gstarh[BN_ * H_];    // gstar fp16 (epre A operand)
__device__ float  g_gstar[BN_ * H_];     // gstar fp32 (context)
__device__ float  g_parts[3 * BN_ * H_]; // split-K partials
__device__ float  g_biascomb[H_];
__device__ float  g_sproj[B_ * A_];
__device__ float  g_scores[BN_];

// ---------------------------------------------------------------------------
__device__ __forceinline__ uint32_t smem_u32(const void* p) {
    uint32_t a;
    asm("{ .reg .u64 t; cvta.to.shared.u64 t, %1; cvt.u32.u64 %0, t; }"
        : "=r"(a) : "l"(p));
    return a;
}
__device__ __forceinline__ float tanh_approx(float x) {
    float y;
    asm("tanh.approx.f32 %0, %1;" : "=f"(y) : "f"(x));
    return y;
}
__device__ __forceinline__ void ldsm4(uint32_t* r, uint32_t addr) {
    asm volatile("ldmatrix.sync.aligned.m8n8.x4.shared.b16 {%0,%1,%2,%3}, [%4];"
                 : "=r"(r[0]), "=r"(r[1]), "=r"(r[2]), "=r"(r[3]) : "r"(addr));
}
__device__ __forceinline__ void mma_f16(float* d, const uint32_t* a,
                                        const uint32_t* b) {
    asm volatile(
        "mma.sync.aligned.m16n8k16.row.col.f32.f16.f16.f32 "
        "{%0,%1,%2,%3}, {%4,%5,%6,%7}, {%8,%9}, {%0,%1,%2,%3};"
        : "+f"(d[0]), "+f"(d[1]), "+f"(d[2]), "+f"(d[3])
        : "r"(a[0]), "r"(a[1]), "r"(a[2]), "r"(a[3]), "r"(b[0]), "r"(b[1]));
}
#define CPA(dst, src) \
    asm volatile("cp.async.cg.shared.global [%0], [%1], 16;" \
                 :: "r"(dst), "l"(src) : "memory")
#define CPCOMMIT() asm volatile("cp.async.commit_group;" ::: "memory")
#define CPWAIT1()  asm volatile("cp.async.wait_group 1;" ::: "memory")
#define CPWAIT0()  asm volatile("cp.async.wait_group 0;" ::: "memory")

// ---------------------------------------------------------------------------
// GEMM core (fp16 operands). FM = A-fragments per warp (M-tile = FM*32).
//   FM=4: block 128x128, 2 CTAs/SM (96KB smem)
//   FM=2: block  64x128, 3 CTAs/SM (72KB smem)
// BK = 64 fp16 elements = 128B rows (same swizzle/addressing as fp32/32).
// Per chunk: 4 k16 steps; 3-stage cp.async ring; fragment double-buffer.
// ---------------------------------------------------------------------------
template <int FM>
struct GemmDims {
    static const int ABYTES = FM * 32 * 128;   // FM*32 rows x 128B
    static const int STAGE  = ABYTES + 16384;  // + B: 128 rows x 128B
    static const int SMEM   = 3 * STAGE;
    static const int OCC    = (FM == 2) ? 3 : 2;
};

#define GEMM_PROLOG(FM)                                                       \
    extern __shared__ char smem[];                                            \
    const uint32_t sb = smem_u32(smem);                                       \
    const int tid = threadIdx.x;                                              \
    const int lane = tid & 31;                                                \
    const int wid = tid >> 5;                                                 \
    const int wr = wid >> 1;   /* 0..1 */                                     \
    const int wc = wid & 1;    /* 0..1 */                                     \
    const int srow = tid >> 3, sc4 = tid & 7;                                 \
    const uint32_t soff0 = (uint32_t)srow * 128 + ((sc4 ^ (srow & 7)) << 4);  \
    const int aRow = wr * (FM * 16) + ((lane >> 3) & 1) * 8 + (lane & 7);     \
    const int cbA = lane >> 4;                                                \
    const uint32_t aBase = (uint32_t)aRow * 128;                              \
    const int rmA = aRow & 7;                                                 \
    const int bRow = wc * 64 + (lane >> 4) * 8 + (lane & 7);                  \
    const int cbB = (lane >> 3) & 1;                                          \
    const uint32_t bBase = (uint32_t)bRow * 128;                              \
    const int rmB = bRow & 7;                                                 \
    float acc[FM][8][4];                                                      \
    _Pragma("unroll") for (int i = 0; i < FM; i++)                            \
        _Pragma("unroll") for (int j = 0; j < 8; j++)                         \
            _Pragma("unroll") for (int q = 0; q < 4; q++) acc[i][j][q] = 0.f;

template <int FM>
__device__ __forceinline__ void gemm_core(
    const __half* __restrict__ pA0, const __half* __restrict__ pB0,
    size_t strideJ, int nch, uint32_t sb, uint32_t soff0,
    uint32_t aBase, int rmA, int cbA,
    uint32_t bBase, int rmB, int cbB,
    float (&acc)[FM][8][4])
{
    const int ABYTES = GemmDims<FM>::ABYTES;
    const int STAGE  = GemmDims<FM>::STAGE;
    const int JA = FM * 2;

    auto issue = [&](uint32_t sbase, int k0) {
        #pragma unroll
        for (int j = 0; j < JA; j++)
            CPA(sbase + soff0 + j * 2048, pA0 + k0 + j * strideJ);
        #pragma unroll
        for (int j = 0; j < 8; j++)
            CPA(sbase + ABYTES + soff0 + j * 2048, pB0 + k0 + j * strideJ);
        CPCOMMIT();
    };

    uint32_t afr[2][FM][4], bfr[2][8][2];

    auto ldA = [&](uint32_t As, int kc, int buf) {
        #pragma unroll
        for (int fm = 0; fm < FM; fm++)
            ldsm4(afr[buf][fm],
                  As + fm * 2048 + aBase + ((((kc * 2) + cbA) ^ rmA) << 4));
    };
    auto ldB = [&](uint32_t Bs, int kc, int buf) {
        #pragma unroll
        for (int p = 0; p < 4; p++) {
            uint32_t t4[4];
            ldsm4(t4, Bs + p * 2048 + bBase + ((((kc * 2) + cbB) ^ rmB) << 4));
            bfr[buf][2*p][0]   = t4[0]; bfr[buf][2*p][1]   = t4[1];
            bfr[buf][2*p+1][0] = t4[2]; bfr[buf][2*p+1][1] = t4[3];
        }
    };

    issue(sb, 0);
    issue(sb + STAGE, 64);
    int cs = 0, is = 2;
    for (int c = 0; c < nch; c++) {
        if (c == nch - 1) { CPWAIT0(); } else { CPWAIT1(); }
        __syncthreads();
        if (c + 2 < nch) {
            issue(sb + is * STAGE, (c + 2) * 64);
            is = (is == 2) ? 0 : is + 1;
        }
        const uint32_t As = sb + cs * STAGE;
        const uint32_t Bs = As + ABYTES;
        ldA(As, 0, 0);
        ldB(Bs, 0, 0);
        #pragma unroll
        for (int kc = 0; kc < 4; kc++) {   // 4 x k16 = 64 elements
            const int cur = kc & 1;
            if (kc < 3) {
                ldA(As, kc + 1, cur ^ 1);
                ldB(Bs, kc + 1, cur ^ 1);
            }
            #pragma unroll
            for (int fm = 0; fm < FM; fm++)
                #pragma unroll
                for (int fn = 0; fn < 8; fn++)
                    mma_f16(acc[fm][fn], afr[cur][fm], bfr[cur][fn]);
        }
        cs = (cs == 2) ? 0 : cs + 1;
    }
}

// ---------------------------------------------------------------------------
// Split-K partial GEMM: Cpart[z] = A @ Bt^T over K slice z (plain stores).
// nchA in 64-element chunks.
// ---------------------------------------------------------------------------
template <int FM>
__global__ __launch_bounds__(128, GemmDims<FM>::OCC)
void mma_gemm_part(const __half* __restrict__ A, const __half* __restrict__ Bt,
                   float* __restrict__ Cparts, size_t zstride,
                   int Nn, int K, int nchA)
{
    const int bm = blockIdx.y * (FM * 32);
    const int bn = blockIdx.x * 128;
    const int z  = blockIdx.z;
    const int kbase = z * nchA * 64;
    int nch = (K >> 6) - z * nchA;
    if (nch > nchA) nch = nchA;
    float* C = Cparts + (size_t)z * zstride;

    GEMM_PROLOG(FM);
    const __half* pA0 = A  + (size_t)(bm + srow) * K + kbase + sc4 * 8;
    const __half* pB0 = Bt + (size_t)(bn + srow) * K + kbase + sc4 * 8;
    const size_t strideJ = (size_t)16 * K;
    gemm_core<FM>(pA0, pB0, strideJ, nch, sb, soff0,
                  aBase, rmA, cbA, bBase, rmB, cbB, acc);

    const int gid = lane >> 2, tig = lane & 3;
    #pragma unroll
    for (int fm = 0; fm < FM; fm++) {
        const int row = bm + wr * (FM * 16) + fm * 16 + gid;
        #pragma unroll
        for (int fn = 0; fn < 8; fn++) {
            const int col = bn + wc * 64 + fn * 8 + tig * 2;
            float2 v01, v23;
            v01.x = acc[fm][fn][0]; v01.y = acc[fm][fn][1];
            v23.x = acc[fm][fn][2]; v23.y = acc[fm][fn][3];
            *(float2*)(C + (size_t)row * Nn + col) = v01;
            *(float2*)(C + (size_t)(row + 8) * Nn + col) = v23;
        }
    }
}

// ---------------------------------------------------------------------------
// Split-K GEMM for skinny M=128 (sproj): C += A @ Bt^T over K slice, atomics.
// klen in elements (multiple of 128 -> nch>=2).
// ---------------------------------------------------------------------------
__global__ __launch_bounds__(128, 2)
void mma_gemm_splitk(const __half* __restrict__ A, const __half* __restrict__ Bt,
                     float* __restrict__ C, int M, int Nn, int K, int klen)
{
    const int bm = blockIdx.y * 128;
    const int bn = blockIdx.x * 128;
    const int kbase = blockIdx.z * klen;
    GEMM_PROLOG(4);
    const __half* pA0 = A  + (size_t)(bm + srow) * K + kbase + sc4 * 8;
    const __half* pB0 = Bt + (size_t)(bn + srow) * K + kbase + sc4 * 8;
    const size_t strideJ = (size_t)16 * K;
    gemm_core<4>(pA0, pB0, strideJ, klen >> 6, sb, soff0,
                 aBase, rmA, cbA, bBase, rmB, cbB, acc);

    const int gid = lane >> 2, tig = lane & 3;
    #pragma unroll
    for (int fm = 0; fm < 4; fm++) {
        const int row = bm + wr * 64 + fm * 16 + gid;
        #pragma unroll
        for (int fn = 0; fn < 8; fn++) {
            const int col = bn + wc * 64 + fn * 8 + tig * 2;
            atomicAdd(C + (size_t)row * Nn + col,       acc[fm][fn][0]);
            atomicAdd(C + (size_t)row * Nn + col + 1,   acc[fm][fn][1]);
            atomicAdd(C + (size_t)(row+8) * Nn + col,   acc[fm][fn][2]);
            atomicAdd(C + (size_t)(row+8) * Nn + col+1, acc[fm][fn][3]);
        }
    }
}

// ---------------------------------------------------------------------------
// Fused e_pre GEMM + scores epilogue (FM=2 tiles, 3 CTAs/SM).
// A = gstarh (fp16), B = WhTh (fp16).
// ---------------------------------------------------------------------------
__global__ __launch_bounds__(128, 3)
void epre_scores_gemm(const __half* __restrict__ A, const __half* __restrict__ Bt,
                      const float* __restrict__ sproj,
                      const float* __restrict__ cov,
                      const float* __restrict__ Wc,
                      const float* __restrict__ v,
                      float* __restrict__ scores)
{
    const int bm = blockIdx.y * 64;
    const int bn = blockIdx.x * 128;
    GEMM_PROLOG(2);
    const __half* pA0 = A  + (size_t)(bm + srow) * H_ + sc4 * 8;
    const __half* pB0 = Bt + (size_t)(bn + srow) * H_ + sc4 * 8;
    const size_t strideJ = (size_t)16 * H_;
    gemm_core<2>(pA0, pB0, strideJ, H_ >> 6, sb, soff0,
                 aBase, rmA, cbA, bBase, rmB, cbB, acc);

    const int gid = lane >> 2, tig = lane & 3;
    float vv[16], wcv[16];
    #pragma unroll
    for (int fn = 0; fn < 8; fn++) {
        const int col = bn + wc * 64 + fn * 8 + tig * 2;
        vv[2*fn]   = v[col];      vv[2*fn+1]  = v[col + 1];
        wcv[2*fn]  = Wc[col];     wcv[2*fn+1] = Wc[col + 1];
    }
    #pragma unroll
    for (int fm = 0; fm < 2; fm++) {
        const int r0 = bm + wr * 32 + fm * 16 + gid;
        const int r1 = r0 + 8;
        const int b0i = r0 / N_, b1i = r1 / N_;
        const float c0 = cov[r0], c1 = cov[r1];
        const float* sp0 = sproj + (size_t)b0i * A_;
        const float* sp1 = sproj + (size_t)b1i * A_;
        float p0 = 0.f, p1 = 0.f;
        #pragma unroll
        for (int fn = 0; fn < 8; fn++) {
            const int col = bn + wc * 64 + fn * 8 + tig * 2;
            p0 += vv[2*fn]   * tanh_approx(acc[fm][fn][0] + sp0[col]     + c0 * wcv[2*fn]);
            p0 += vv[2*fn+1] * tanh_approx(acc[fm][fn][1] + sp0[col + 1] + c0 * wcv[2*fn+1]);
            p1 += vv[2*fn]   * tanh_approx(acc[fm][fn][2] + sp1[col]     + c1 * wcv[2*fn]);
            p1 += vv[2*fn+1] * tanh_approx(acc[fm][fn][3] + sp1[col + 1] + c1 * wcv[2*fn+1]);
        }
        p0 += __shfl_xor_sync(0xffffffffu, p0, 1);
        p0 += __shfl_xor_sync(0xffffffffu, p0, 2);
        p1 += __shfl_xor_sync(0xffffffffu, p1, 1);
        p1 += __shfl_xor_sync(0xffffffffu, p1, 2);
        if (tig == 0) {
            atomicAdd(scores + r0, p0);
            atomicAdd(scores + r1, p1);
        }
    }
}

// ---------------------------------------------------------------------------
// Reductions over split-K partials.
// ---------------------------------------------------------------------------
// WcombTh = fp16(p0 + p1)
__global__ __launch_bounds__(256) void reduce2_half_kernel(
    const float* __restrict__ p0, const float* __restrict__ p1,
    __half* __restrict__ out)
{
    const size_t i = ((size_t)blockIdx.x * 256 + threadIdx.x) * 4;
    float4 a = *(const float4*)(p0 + i);
    float4 b = *(const float4*)(p1 + i);
    __half2 h0 = __floats2half2_rn(a.x + b.x, a.y + b.y);
    __half2 h1 = __floats2half2_rn(a.z + b.z, a.w + b.w);
    *(__half2*)(out + i)     = h0;
    *(__half2*)(out + i + 2) = h1;
}

// gstar = p0+p1+p2+bias (fp32) AND gstarh = fp16(gstar)
__global__ __launch_bounds__(256) void reduce3_bias_kernel(
    const float* __restrict__ p0, const float* __restrict__ p1,
    const float* __restrict__ p2, const float* __restrict__ bias,
    float* __restrict__ outf, __half* __restrict__ outh)
{
    const size_t i = ((size_t)blockIdx.x * 256 + threadIdx.x) * 4;
    const int col = (int)(i & (H_ - 1));
    float4 a = *(const float4*)(p0 + i);
    float4 b = *(const float4*)(p1 + i);
    float4 c = *(const float4*)(p2 + i);
    float4 d = *(const float4*)(bias + col);
    float4 r;
    r.x = a.x + b.x + c.x + d.x;
    r.y = a.y + b.y + c.y + d.y;
    r.z = a.z + b.z + c.z + d.z;
    r.w = a.w + b.w + c.w + d.w;
    *(float4*)(outf + i) = r;
    *(__half2*)(outh + i)     = __floats2half2_rn(r.x, r.y);
    *(__half2*)(outh + i + 2) = __floats2half2_rn(r.z, r.w);
}

// ---------------------------------------------------------------------------
// Batched prologue: fp16 transposes, zero-fills, fp16 conversions, bias init.
// ---------------------------------------------------------------------------
#define PREP_T1 4096                       // WgsT (4096x1024 -> T)
#define PREP_T2 (PREP_T1 + 1024)           // WhT
#define PREP_T3 (PREP_T2 + 1024)           // WsT
#define PREP_ZS (PREP_T3 + 25)             // zero scores
#define PREP_ZP (PREP_ZS + 512)            // zero sproj
#define PREP_CS (PREP_ZP + 64)             // s_t -> fp16 (131072/2048)
#define PREP_BI (PREP_CS + 4)              // bias init
#define PREP_CX (PREP_BI + 12544)          // X -> fp16 (25690112/2048)
#define PREP_CW (PREP_CX + 8192)           // W_g -> fp16 (16777216/2048)
#define PREP_END PREP_CW

__device__ __forceinline__ void conv8(const float* __restrict__ in,
                                      __half* __restrict__ out, size_t i8) {
    float4 a = *(const float4*)(in + i8);
    float4 b = *(const float4*)(in + i8 + 4);
    __half2 h[4];
    h[0] = __floats2half2_rn(a.x, a.y);
    h[1] = __floats2half2_rn(a.z, a.w);
    h[2] = __floats2half2_rn(b.x, b.y);
    h[3] = __floats2half2_rn(b.z, b.w);
    *(uint4*)(out + i8) = *(const uint4*)h;
}

__device__ __forceinline__ void do_transpose32h(
    const float* __restrict__ in, __half* __restrict__ out,
    int R, int C, int tx, int ty)
{
    __shared__ float t[32][33];
    const int c0 = tx * 32, r0 = ty * 32;
    const int x = threadIdx.x & 31, y = (threadIdx.x >> 5);
    #pragma unroll
    for (int j = 0; j < 32; j += 8)
        t[y + j][x] = in[(size_t)(r0 + y + j) * C + c0 + x];
    __syncthreads();
    #pragma unroll
    for (int j = 0; j < 32; j += 8)
        out[(size_t)(c0 + y + j) * R + r0 + x] = __float2half_rn(t[x][y + j]);
}

__global__ __launch_bounds__(256) void prep_kernel(
    const float* __restrict__ W_gs, __half* __restrict__ WgsTh,
    const float* __restrict__ W_h,  __half* __restrict__ WhTh,
    const float* __restrict__ W_s,  __half* __restrict__ WsTh,
    const float* __restrict__ s_t,  __half* __restrict__ sth,
    const float* __restrict__ X,    __half* __restrict__ Xh,
    const float* __restrict__ W_g,  __half* __restrict__ Wgh,
    const float* __restrict__ b_gs, float* __restrict__ biascomb,
    float* __restrict__ scores, float* __restrict__ sproj)
{
    const int bid = blockIdx.x;
    if (bid < PREP_T1) {
        do_transpose32h(W_gs, WgsTh, G_, H_, bid & 31, bid >> 5);
    } else if (bid < PREP_T2) {
        const int b = bid - PREP_T1;
        do_transpose32h(W_h, WhTh, H_, A_, b & 31, b >> 5);
    } else if (bid < PREP_T3) {
        const int b = bid - PREP_T2;
        do_transpose32h(W_s, WsTh, H_, A_, b & 31, b >> 5);
    } else if (bid < PREP_ZS) {
        const int i = (bid - PREP_T3) * 256 + threadIdx.x;
        if (i < BN_) scores[i] = 0.f;
    } else if (bid < PREP_ZP) {
        const int i = (bid - PREP_ZS) * 256 + threadIdx.x;
        sproj[i] = 0.f;
    } else if (bid < PREP_CS) {
        conv8(s_t, sth, ((size_t)(bid - PREP_ZP) * 256 + threadIdx.x) * 8);
    } else if (bid < PREP_BI) {
        const int h = (bid - PREP_CS) * 256 + threadIdx.x;
        biascomb[h] = b_gs[h];
    } else if (bid < PREP_CX) {
        conv8(X, Xh, ((size_t)(bid - PREP_BI) * 256 + threadIdx.x) * 8);
    } else {
        conv8(W_g, Wgh, ((size_t)(bid - PREP_CX) * 256 + threadIdx.x) * 8);
    }
}

__global__ void bias_acc_kernel(const float* __restrict__ b_g,
                                const float* __restrict__ W_gs,
                                float* __restrict__ bias) {
    int h = blockIdx.x * blockDim.x + threadIdx.x;
    int k0 = blockIdx.y * 256;
    float acc = 0.f;
    #pragma unroll 4
    for (int k = k0; k < k0 + 256; k++)
        acc += b_g[k] * W_gs[(size_t)k * H_ + h];
    atomicAdd(&bias[h], acc);
}

// softmax over N=49 + context c[b,h] = sum_n alpha[n] * gstar[b,n,h]
__global__ __launch_bounds__(256) void context_kernel(
    const float* __restrict__ scores, const float* __restrict__ gstar,
    float* __restrict__ out)
{
    const int b = blockIdx.x;
    __shared__ float alpha[N_];
    const int tid = threadIdx.x;

    if (tid == 0) {
        float m = -1e30f;
        #pragma unroll
        for (int n = 0; n < N_; n++) m = fmaxf(m, scores[b * N_ + n]);
        float s = 0.f;
        #pragma unroll
        for (int n = 0; n < N_; n++) {
            float e = expf(scores[b * N_ + n] - m);
            alpha[n] = e;
            s += e;
        }
        float inv = 1.f / s;
        #pragma unroll
        for (int n = 0; n < N_; n++) alpha[n] *= inv;
    }
    __syncthreads();

    const float* gb = gstar + (size_t)b * N_ * H_;
    for (int h = tid; h < H_; h += 256) {
        float acc = 0.f;
        #pragma unroll
        for (int n = 0; n < N_; n++)
            acc += alpha[n] * gb[(size_t)n * H_ + h];
        out[(size_t)b * H_ + h] = acc;
    }
}

// ---------------------------------------------------------------------------
extern "C" void kernel_launch(void* const* d_in, const int* in_sizes, int n_in,
                              void* d_out, int out_size) {
    const float* X    = (const float*)d_in[0];   // [6272,4096]
    const float* s_t  = (const float*)d_in[1];   // [128,1024]
    const float* cov  = (const float*)d_in[2];   // [6272]
    const float* W_g  = (const float*)d_in[3];   // [4096,4096]
    const float* b_g  = (const float*)d_in[4];   // [4096]
    const float* W_gs = (const float*)d_in[5];   // [4096,1024]
    const float* b_gs = (const float*)d_in[6];   // [1024]
    const float* W_h  = (const float*)d_in[7];   // [1024,1024]
    const float* W_s  = (const float*)d_in[8];   // [1024,1024]
    const float* W_c  = (const float*)d_in[9];   // [1024]
    const float* v    = (const float*)d_in[10];  // [1024]
    float* out = (float*)d_out;                  // [128,1024]

    __half *Xh, *Wgh, *WgsTh, *WcombTh, *WhTh, *WsTh, *sth, *gstarh;
    float *gstar, *parts, *biascomb, *sproj, *scores;
    cudaGetSymbolAddress((void**)&Xh,       g_Xh);
    cudaGetSymbolAddress((void**)&Wgh,      g_Wgh);
    cudaGetSymbolAddress((void**)&WgsTh,    g_WgsTh);
    cudaGetSymbolAddress((void**)&WcombTh,  g_WcombTh);
    cudaGetSymbolAddress((void**)&WhTh,     g_WhTh);
    cudaGetSymbolAddress((void**)&WsTh,     g_WsTh);
    cudaGetSymbolAddress((void**)&sth,      g_sth);
    cudaGetSymbolAddress((void**)&gstarh,   g_gstarh);
    cudaGetSymbolAddress((void**)&gstar,    g_gstar);
    cudaGetSymbolAddress((void**)&parts,    g_parts);
    cudaGetSymbolAddress((void**)&biascomb, g_biascomb);
    cudaGetSymbolAddress((void**)&sproj,    g_sproj);
    cudaGetSymbolAddress((void**)&scores,   g_scores);

    const int SM4 = GemmDims<4>::SMEM;   // 96KB
    const int SM2 = GemmDims<2>::SMEM;   // 72KB
    cudaFuncSetAttribute(mma_gemm_part<4>,
                         cudaFuncAttributeMaxDynamicSharedMemorySize, SM4);
    cudaFuncSetAttribute(mma_gemm_splitk,
                         cudaFuncAttributeMaxDynamicSharedMemorySize, SM4);
    cudaFuncSetAttribute(epre_scores_gemm,
                         cudaFuncAttributeMaxDynamicSharedMemorySize, SM2);

    // prologue: fp16 transposes + conversions, zero-fills, bias init
    prep_kernel<<<PREP_END, 256>>>(W_gs, WgsTh, W_h, WhTh, W_s, WsTh,
                                   s_t, sth, X, Xh, W_g, Wgh,
                                   b_gs, biascomb, scores, sproj);
    bias_acc_kernel<<<dim3(H_ / 256, G_ / 256), 256>>>(b_g, W_gs, biascomb);

    // WcombT = WgsT @ W_g^T, split-K x2 (32+32 chunks of 64), reduce->fp16
    mma_gemm_part<4><<<dim3(G_ / 128, H_ / 128, 2), 128, SM4>>>(
        WgsTh, Wgh, parts, (size_t)H_ * G_, G_, G_, 32);
    reduce2_half_kernel<<<(H_ * G_ / 4) / 256, 256>>>(
        parts, parts + (size_t)H_ * G_, WcombTh);

    // gstar partials = X @ WcombT^T, split-K x3 (22/22/20 chunks of 64)
    mma_gemm_part<4><<<dim3(H_ / 128, BN_ / 128, 3), 128, SM4>>>(
        Xh, WcombTh, parts, (size_t)BN_ * H_, H_, G_, 22);
    // gstar = p0+p1+p2 + biascomb (fp32 + fp16 copies)
    reduce3_bias_kernel<<<(BN_ * H_ / 4) / 256, 256>>>(
        parts, parts + (size_t)BN_ * H_, parts + 2 * (size_t)BN_ * H_,
        biascomb, gstar, gstarh);

    // s_proj = sth @ WsT^T   (split-K x8 of 128 elems, atomic)
    mma_gemm_splitk<<<dim3(A_ / 128, 1, 8), 128, SM4>>>(
        sth, WsTh, sproj, B_, A_, H_, H_ / 8);

    // fused: e_pre + tanh + v-dot -> scores
    epre_scores_gemm<<<dim3(A_ / 128, BN_ / 64), 128, SM2>>>(
        gstarh, WhTh, sproj, cov, W_c, v, scores);

    context_kernel<<<B_, 256>>>(scores, gstar, out);
}

// round 15
// speedup vs baseline: 1.5741x; 1.0560x over previous
#include <cuda_runtime.h>
#include <cuda_fp16.h>
#include <math.h>
#include <stdint.h>

// ===========================================================================
// img_attention via warp-level FP16 mma.sync m16n8k16 (compute_103-safe)
//   c_img = softmax(v . tanh(Wh g* + Ws s + Wc cov)) @ g*
//   g*    = X @ (W_g @ W_gs) + (b_g @ W_gs + b_gs)      [algebraic fold]
// R14: Wcomb single-pass (no split/reduce), gstar stored fp16-only,
//      bias_acc folded into prep (memset + atomics), fewer launches.
// ===========================================================================

#define B_   128
#define N_   49
#define G_   4096
#define H_   1024
#define A_   1024
#define BN_  (B_ * N_)   // 6272

__device__ __half g_Xh[BN_ * G_];        // X fp16
__device__ __half g_Wgh[G_ * G_];        // W_g fp16
__device__ __half g_WgsTh[H_ * G_];      // W_gs^T fp16
__device__ __half g_WcombTh[H_ * G_];    // (W_g@W_gs)^T fp16
__device__ __half g_WhTh[A_ * H_];       // W_h^T fp16
__device__ __half g_WsTh[A_ * H_];       // W_s^T fp16
__device__ __half g_sth[B_ * H_];        // s_t fp16
__device__ __half g_gstarh[BN_ * H_];    // gstar fp16 (epre A + context)
__device__ float  g_parts[3 * BN_ * H_]; // split-K partials (gstar)
__device__ float  g_biascomb[H_];        // b_g @ W_gs (zeroed via memset)
__device__ float  g_sproj[B_ * A_];
__device__ float  g_scores[BN_];

// ---------------------------------------------------------------------------
__device__ __forceinline__ uint32_t smem_u32(const void* p) {
    uint32_t a;
    asm("{ .reg .u64 t; cvta.to.shared.u64 t, %1; cvt.u32.u64 %0, t; }"
        : "=r"(a) : "l"(p));
    return a;
}
__device__ __forceinline__ float tanh_approx(float x) {
    float y;
    asm("tanh.approx.f32 %0, %1;" : "=f"(y) : "f"(x));
    return y;
}
__device__ __forceinline__ void ldsm4(uint32_t* r, uint32_t addr) {
    asm volatile("ldmatrix.sync.aligned.m8n8.x4.shared.b16 {%0,%1,%2,%3}, [%4];"
                 : "=r"(r[0]), "=r"(r[1]), "=r"(r[2]), "=r"(r[3]) : "r"(addr));
}
__device__ __forceinline__ void mma_f16(float* d, const uint32_t* a,
                                        const uint32_t* b) {
    asm volatile(
        "mma.sync.aligned.m16n8k16.row.col.f32.f16.f16.f32 "
        "{%0,%1,%2,%3}, {%4,%5,%6,%7}, {%8,%9}, {%0,%1,%2,%3};"
        : "+f"(d[0]), "+f"(d[1]), "+f"(d[2]), "+f"(d[3])
        : "r"(a[0]), "r"(a[1]), "r"(a[2]), "r"(a[3]), "r"(b[0]), "r"(b[1]));
}
#define CPA(dst, src) \
    asm volatile("cp.async.cg.shared.global [%0], [%1], 16;" \
                 :: "r"(dst), "l"(src) : "memory")
#define CPCOMMIT() asm volatile("cp.async.commit_group;" ::: "memory")
#define CPWAIT1()  asm volatile("cp.async.wait_group 1;" ::: "memory")
#define CPWAIT0()  asm volatile("cp.async.wait_group 0;" ::: "memory")

// ---------------------------------------------------------------------------
// GEMM core (fp16). FM = A-fragments per warp (M-tile = FM*32).
// BK = 64 fp16 = 128B rows. 3-stage cp.async ring, frag double-buffer.
// ---------------------------------------------------------------------------
template <int FM>
struct GemmDims {
    static const int ABYTES = FM * 32 * 128;
    static const int STAGE  = ABYTES + 16384;
    static const int SMEM   = 3 * STAGE;
    static const int OCC    = (FM == 2) ? 3 : 2;
};

#define GEMM_PROLOG(FM)                                                       \
    extern __shared__ char smem[];                                            \
    const uint32_t sb = smem_u32(smem);                                       \
    const int tid = threadIdx.x;                                              \
    const int lane = tid & 31;                                                \
    const int wid = tid >> 5;                                                 \
    const int wr = wid >> 1;                                                  \
    const int wc = wid & 1;                                                   \
    const int srow = tid >> 3, sc4 = tid & 7;                                 \
    const uint32_t soff0 = (uint32_t)srow * 128 + ((sc4 ^ (srow & 7)) << 4);  \
    const int aRow = wr * (FM * 16) + ((lane >> 3) & 1) * 8 + (lane & 7);     \
    const int cbA = lane >> 4;                                                \
    const uint32_t aBase = (uint32_t)aRow * 128;                              \
    const int rmA = aRow & 7;                                                 \
    const int bRow = wc * 64 + (lane >> 4) * 8 + (lane & 7);                  \
    const int cbB = (lane >> 3) & 1;                                          \
    const uint32_t bBase = (uint32_t)bRow * 128;                              \
    const int rmB = bRow & 7;                                                 \
    float acc[FM][8][4];                                                      \
    _Pragma("unroll") for (int i = 0; i < FM; i++)                            \
        _Pragma("unroll") for (int j = 0; j < 8; j++)                         \
            _Pragma("unroll") for (int q = 0; q < 4; q++) acc[i][j][q] = 0.f;

template <int FM>
__device__ __forceinline__ void gemm_core(
    const __half* __restrict__ pA0, const __half* __restrict__ pB0,
    size_t strideJ, int nch, uint32_t sb, uint32_t soff0,
    uint32_t aBase, int rmA, int cbA,
    uint32_t bBase, int rmB, int cbB,
    float (&acc)[FM][8][4])
{
    const int ABYTES = GemmDims<FM>::ABYTES;
    const int STAGE  = GemmDims<FM>::STAGE;
    const int JA = FM * 2;

    auto issue = [&](uint32_t sbase, int k0) {
        #pragma unroll
        for (int j = 0; j < JA; j++)
            CPA(sbase + soff0 + j * 2048, pA0 + k0 + j * strideJ);
        #pragma unroll
        for (int j = 0; j < 8; j++)
            CPA(sbase + ABYTES + soff0 + j * 2048, pB0 + k0 + j * strideJ);
        CPCOMMIT();
    };

    uint32_t afr[2][FM][4], bfr[2][8][2];

    auto ldA = [&](uint32_t As, int kc, int buf) {
        #pragma unroll
        for (int fm = 0; fm < FM; fm++)
            ldsm4(afr[buf][fm],
                  As + fm * 2048 + aBase + ((((kc * 2) + cbA) ^ rmA) << 4));
    };
    auto ldB = [&](uint32_t Bs, int kc, int buf) {
        #pragma unroll
        for (int p = 0; p < 4; p++) {
            uint32_t t4[4];
            ldsm4(t4, Bs + p * 2048 + bBase + ((((kc * 2) + cbB) ^ rmB) << 4));
            bfr[buf][2*p][0]   = t4[0]; bfr[buf][2*p][1]   = t4[1];
            bfr[buf][2*p+1][0] = t4[2]; bfr[buf][2*p+1][1] = t4[3];
        }
    };

    issue(sb, 0);
    issue(sb + STAGE, 64);
    int cs = 0, is = 2;
    for (int c = 0; c < nch; c++) {
        if (c == nch - 1) { CPWAIT0(); } else { CPWAIT1(); }
        __syncthreads();
        if (c + 2 < nch) {
            issue(sb + is * STAGE, (c + 2) * 64);
            is = (is == 2) ? 0 : is + 1;
        }
        const uint32_t As = sb + cs * STAGE;
        const uint32_t Bs = As + ABYTES;
        ldA(As, 0, 0);
        ldB(Bs, 0, 0);
        #pragma unroll
        for (int kc = 0; kc < 4; kc++) {
            const int cur = kc & 1;
            if (kc < 3) {
                ldA(As, kc + 1, cur ^ 1);
                ldB(Bs, kc + 1, cur ^ 1);
            }
            #pragma unroll
            for (int fm = 0; fm < FM; fm++)
                #pragma unroll
                for (int fn = 0; fn < 8; fn++)
                    mma_f16(acc[fm][fn], afr[cur][fm], bfr[cur][fn]);
        }
        cs = (cs == 2) ? 0 : cs + 1;
    }
}

// ---------------------------------------------------------------------------
// Full-K GEMM with direct fp16 store (Wcomb): Ch = fp16(A @ Bt^T).
// ---------------------------------------------------------------------------
__global__ __launch_bounds__(128, 2)
void mma_gemm_h(const __half* __restrict__ A, const __half* __restrict__ Bt,
                __half* __restrict__ Ch, int Nn, int K)
{
    const int bm = blockIdx.y * 128;
    const int bn = blockIdx.x * 128;
    GEMM_PROLOG(4);
    const __half* pA0 = A  + (size_t)(bm + srow) * K + sc4 * 8;
    const __half* pB0 = Bt + (size_t)(bn + srow) * K + sc4 * 8;
    const size_t strideJ = (size_t)16 * K;
    gemm_core<4>(pA0, pB0, strideJ, K >> 6, sb, soff0,
                 aBase, rmA, cbA, bBase, rmB, cbB, acc);

    const int gid = lane >> 2, tig = lane & 3;
    #pragma unroll
    for (int fm = 0; fm < 4; fm++) {
        const int row = bm + wr * 64 + fm * 16 + gid;
        #pragma unroll
        for (int fn = 0; fn < 8; fn++) {
            const int col = bn + wc * 64 + fn * 8 + tig * 2;
            *(__half2*)(Ch + (size_t)row * Nn + col) =
                __floats2half2_rn(acc[fm][fn][0], acc[fm][fn][1]);
            *(__half2*)(Ch + (size_t)(row + 8) * Nn + col) =
                __floats2half2_rn(acc[fm][fn][2], acc[fm][fn][3]);
        }
    }
}

// ---------------------------------------------------------------------------
// Split-K partial GEMM (gstar): Cpart[z] = A @ Bt^T over K slice z.
// ---------------------------------------------------------------------------
__global__ __launch_bounds__(128, 2)
void mma_gemm_part(const __half* __restrict__ A, const __half* __restrict__ Bt,
                   float* __restrict__ Cparts, size_t zstride,
                   int Nn, int K, int nchA)
{
    const int bm = blockIdx.y * 128;
    const int bn = blockIdx.x * 128;
    const int z  = blockIdx.z;
    const int kbase = z * nchA * 64;
    int nch = (K >> 6) - z * nchA;
    if (nch > nchA) nch = nchA;
    float* C = Cparts + (size_t)z * zstride;

    GEMM_PROLOG(4);
    const __half* pA0 = A  + (size_t)(bm + srow) * K + kbase + sc4 * 8;
    const __half* pB0 = Bt + (size_t)(bn + srow) * K + kbase + sc4 * 8;
    const size_t strideJ = (size_t)16 * K;
    gemm_core<4>(pA0, pB0, strideJ, nch, sb, soff0,
                 aBase, rmA, cbA, bBase, rmB, cbB, acc);

    const int gid = lane >> 2, tig = lane & 3;
    #pragma unroll
    for (int fm = 0; fm < 4; fm++) {
        const int row = bm + wr * 64 + fm * 16 + gid;
        #pragma unroll
        for (int fn = 0; fn < 8; fn++) {
            const int col = bn + wc * 64 + fn * 8 + tig * 2;
            float2 v01, v23;
            v01.x = acc[fm][fn][0]; v01.y = acc[fm][fn][1];
            v23.x = acc[fm][fn][2]; v23.y = acc[fm][fn][3];
            *(float2*)(C + (size_t)row * Nn + col) = v01;
            *(float2*)(C + (size_t)(row + 8) * Nn + col) = v23;
        }
    }
}

// ---------------------------------------------------------------------------
// Split-K GEMM for skinny M=128 (sproj): atomics into zeroed C.
// ---------------------------------------------------------------------------
__global__ __launch_bounds__(128, 2)
void mma_gemm_splitk(const __half* __restrict__ A, const __half* __restrict__ Bt,
                     float* __restrict__ C, int M, int Nn, int K, int klen)
{
    const int bm = blockIdx.y * 128;
    const int bn = blockIdx.x * 128;
    const int kbase = blockIdx.z * klen;
    GEMM_PROLOG(4);
    const __half* pA0 = A  + (size_t)(bm + srow) * K + kbase + sc4 * 8;
    const __half* pB0 = Bt + (size_t)(bn + srow) * K + kbase + sc4 * 8;
    const size_t strideJ = (size_t)16 * K;
    gemm_core<4>(pA0, pB0, strideJ, klen >> 6, sb, soff0,
                 aBase, rmA, cbA, bBase, rmB, cbB, acc);

    const int gid = lane >> 2, tig = lane & 3;
    #pragma unroll
    for (int fm = 0; fm < 4; fm++) {
        const int row = bm + wr * 64 + fm * 16 + gid;
        #pragma unroll
        for (int fn = 0; fn < 8; fn++) {
            const int col = bn + wc * 64 + fn * 8 + tig * 2;
            atomicAdd(C + (size_t)row * Nn + col,       acc[fm][fn][0]);
            atomicAdd(C + (size_t)row * Nn + col + 1,   acc[fm][fn][1]);
            atomicAdd(C + (size_t)(row+8) * Nn + col,   acc[fm][fn][2]);
            atomicAdd(C + (size_t)(row+8) * Nn + col+1, acc[fm][fn][3]);
        }
    }
}

// ---------------------------------------------------------------------------
// Fused e_pre GEMM + scores epilogue (FM=2 tiles, 3 CTAs/SM).
// ---------------------------------------------------------------------------
__global__ __launch_bounds__(128, 3)
void epre_scores_gemm(const __half* __restrict__ A, const __half* __restrict__ Bt,
                      const float* __restrict__ sproj,
                      const float* __restrict__ cov,
                      const float* __restrict__ Wc,
                      const float* __restrict__ v,
                      float* __restrict__ scores)
{
    const int bm = blockIdx.y * 64;
    const int bn = blockIdx.x * 128;
    GEMM_PROLOG(2);
    const __half* pA0 = A  + (size_t)(bm + srow) * H_ + sc4 * 8;
    const __half* pB0 = Bt + (size_t)(bn + srow) * H_ + sc4 * 8;
    const size_t strideJ = (size_t)16 * H_;
    gemm_core<2>(pA0, pB0, strideJ, H_ >> 6, sb, soff0,
                 aBase, rmA, cbA, bBase, rmB, cbB, acc);

    const int gid = lane >> 2, tig = lane & 3;
    float vv[16], wcv[16];
    #pragma unroll
    for (int fn = 0; fn < 8; fn++) {
        const int col = bn + wc * 64 + fn * 8 + tig * 2;
        vv[2*fn]   = v[col];      vv[2*fn+1]  = v[col + 1];
        wcv[2*fn]  = Wc[col];     wcv[2*fn+1] = Wc[col + 1];
    }
    #pragma unroll
    for (int fm = 0; fm < 2; fm++) {
        const int r0 = bm + wr * 32 + fm * 16 + gid;
        const int r1 = r0 + 8;
        const int b0i = r0 / N_, b1i = r1 / N_;
        const float c0 = cov[r0], c1 = cov[r1];
        const float* sp0 = sproj + (size_t)b0i * A_;
        const float* sp1 = sproj + (size_t)b1i * A_;
        float p0 = 0.f, p1 = 0.f;
        #pragma unroll
        for (int fn = 0; fn < 8; fn++) {
            const int col = bn + wc * 64 + fn * 8 + tig * 2;
            p0 += vv[2*fn]   * tanh_approx(acc[fm][fn][0] + sp0[col]     + c0 * wcv[2*fn]);
            p0 += vv[2*fn+1] * tanh_approx(acc[fm][fn][1] + sp0[col + 1] + c0 * wcv[2*fn+1]);
            p1 += vv[2*fn]   * tanh_approx(acc[fm][fn][2] + sp1[col]     + c1 * wcv[2*fn]);
            p1 += vv[2*fn+1] * tanh_approx(acc[fm][fn][3] + sp1[col + 1] + c1 * wcv[2*fn+1]);
        }
        p0 += __shfl_xor_sync(0xffffffffu, p0, 1);
        p0 += __shfl_xor_sync(0xffffffffu, p0, 2);
        p1 += __shfl_xor_sync(0xffffffffu, p1, 1);
        p1 += __shfl_xor_sync(0xffffffffu, p1, 2);
        if (tig == 0) {
            atomicAdd(scores + r0, p0);
            atomicAdd(scores + r1, p1);
        }
    }
}

// ---------------------------------------------------------------------------
// gstarh = fp16(p0+p1+p2 + biascomb[col] + b_gs[col])
// ---------------------------------------------------------------------------
__global__ __launch_bounds__(256) void reduce3_bias_kernel(
    const float* __restrict__ p0, const float* __restrict__ p1,
    const float* __restrict__ p2, const float* __restrict__ biascomb,
    const float* __restrict__ b_gs, __half* __restrict__ outh)
{
    const size_t i = ((size_t)blockIdx.x * 256 + threadIdx.x) * 4;
    const int col = (int)(i & (H_ - 1));
    float4 a = *(const float4*)(p0 + i);
    float4 b = *(const float4*)(p1 + i);
    float4 c = *(const float4*)(p2 + i);
    float4 d = *(const float4*)(biascomb + col);
    float4 e = *(const float4*)(b_gs + col);
    *(__half2*)(outh + i) =
        __floats2half2_rn(a.x + b.x + c.x + d.x + e.x,
                          a.y + b.y + c.y + d.y + e.y);
    *(__half2*)(outh + i + 2) =
        __floats2half2_rn(a.z + b.z + c.z + d.z + e.z,
                          a.w + b.w + c.w + d.w + e.w);
}

// ---------------------------------------------------------------------------
// Batched prologue: fp16 transposes/conversions, zero-fills, bias_acc.
// biascomb must be zeroed (cudaMemsetAsync) before this kernel.
// ---------------------------------------------------------------------------
#define PREP_T1 4096                        // W_gs transpose
#define PREP_T2 (PREP_T1 + 1024)            // W_h transpose
#define PREP_T3 (PREP_T2 + 1024)            // W_s transpose
#define PREP_ZS (PREP_T3 + 25)              // zero scores
#define PREP_ZP (PREP_ZS + 512)             // zero sproj
#define PREP_CS (PREP_ZP + 64)              // s_t -> fp16
#define PREP_CX (PREP_CS + 12544)           // X -> fp16
#define PREP_CW (PREP_CX + 8192)            // W_g -> fp16
#define PREP_BA (PREP_CW + 64)              // bias_acc (4 h x 16 k blocks)
#define PREP_END PREP_BA

__device__ __forceinline__ void conv8(const float* __restrict__ in,
                                      __half* __restrict__ out, size_t i8) {
    float4 a = *(const float4*)(in + i8);
    float4 b = *(const float4*)(in + i8 + 4);
    __half2 h[4];
    h[0] = __floats2half2_rn(a.x, a.y);
    h[1] = __floats2half2_rn(a.z, a.w);
    h[2] = __floats2half2_rn(b.x, b.y);
    h[3] = __floats2half2_rn(b.z, b.w);
    *(uint4*)(out + i8) = *(const uint4*)h;
}

__device__ __forceinline__ void do_transpose32h(
    const float* __restrict__ in, __half* __restrict__ out,
    int R, int C, int tx, int ty)
{
    __shared__ float t[32][33];
    const int c0 = tx * 32, r0 = ty * 32;
    const int x = threadIdx.x & 31, y = (threadIdx.x >> 5);
    #pragma unroll
    for (int j = 0; j < 32; j += 8)
        t[y + j][x] = in[(size_t)(r0 + y + j) * C + c0 + x];
    __syncthreads();
    #pragma unroll
    for (int j = 0; j < 32; j += 8)
        out[(size_t)(c0 + y + j) * R + r0 + x] = __float2half_rn(t[x][y + j]);
}

__global__ __launch_bounds__(256) void prep_kernel(
    const float* __restrict__ W_gs, __half* __restrict__ WgsTh,
    const float* __restrict__ W_h,  __half* __restrict__ WhTh,
    const float* __restrict__ W_s,  __half* __restrict__ WsTh,
    const float* __restrict__ s_t,  __half* __restrict__ sth,
    const float* __restrict__ X,    __half* __restrict__ Xh,
    const float* __restrict__ W_g,  __half* __restrict__ Wgh,
    const float* __restrict__ b_g,  float* __restrict__ biascomb,
    float* __restrict__ scores, float* __restrict__ sproj)
{
    const int bid = blockIdx.x;
    if (bid < PREP_T1) {
        do_transpose32h(W_gs, WgsTh, G_, H_, bid & 31, bid >> 5);
    } else if (bid < PREP_T2) {
        const int b = bid - PREP_T1;
        do_transpose32h(W_h, WhTh, H_, A_, b & 31, b >> 5);
    } else if (bid < PREP_T3) {
        const int b = bid - PREP_T2;
        do_transpose32h(W_s, WsTh, H_, A_, b & 31, b >> 5);
    } else if (bid < PREP_ZS) {
        const int i = (bid - PREP_T3) * 256 + threadIdx.x;
        if (i < BN_) scores[i] = 0.f;
    } else if (bid < PREP_ZP) {
        const int i = (bid - PREP_ZS) * 256 + threadIdx.x;
        sproj[i] = 0.f;
    } else if (bid < PREP_CS) {
        conv8(s_t, sth, ((size_t)(bid - PREP_ZP) * 256 + threadIdx.x) * 8);
    } else if (bid < PREP_CX) {
        conv8(X, Xh, ((size_t)(bid - PREP_CS) * 256 + threadIdx.x) * 8);
    } else if (bid < PREP_CW) {
        conv8(W_g, Wgh, ((size_t)(bid - PREP_CX) * 256 + threadIdx.x) * 8);
    } else {
        // bias_acc: biascomb[h] += sum over 256-k slice of b_g[k]*W_gs[k,h]
        const int b = bid - PREP_CW;        // 0..63
        const int h = (b & 3) * 256 + threadIdx.x;
        const int k0 = (b >> 2) * 256;
        float acc = 0.f;
        #pragma unroll 4
        for (int k = k0; k < k0 + 256; k++)
            acc += b_g[k] * W_gs[(size_t)k * H_ + h];
        atomicAdd(&biascomb[h], acc);
    }
}

// softmax over N=49 + context c[b,h] = sum_n alpha[n] * gstarh[b,n,h]
__global__ __launch_bounds__(256) void context_kernel(
    const float* __restrict__ scores, const __half* __restrict__ gstarh,
    float* __restrict__ out)
{
    const int b = blockIdx.x;
    __shared__ float alpha[N_];
    const int tid = threadIdx.x;

    if (tid == 0) {
        float m = -1e30f;
        #pragma unroll
        for (int n = 0; n < N_; n++) m = fmaxf(m, scores[b * N_ + n]);
        float s = 0.f;
        #pragma unroll
        for (int n = 0; n < N_; n++) {
            float e = expf(scores[b * N_ + n] - m);
            alpha[n] = e;
            s += e;
        }
        float inv = 1.f / s;
        #pragma unroll
        for (int n = 0; n < N_; n++) alpha[n] *= inv;
    }
    __syncthreads();

    const __half* gb = gstarh + (size_t)b * N_ * H_;
    for (int h = tid; h < H_; h += 256) {
        float acc = 0.f;
        #pragma unroll
        for (int n = 0; n < N_; n++)
            acc += alpha[n] * __half2float(gb[(size_t)n * H_ + h]);
        out[(size_t)b * H_ + h] = acc;
    }
}

// ---------------------------------------------------------------------------
extern "C" void kernel_launch(void* const* d_in, const int* in_sizes, int n_in,
                              void* d_out, int out_size) {
    const float* X    = (const float*)d_in[0];   // [6272,4096]
    const float* s_t  = (const float*)d_in[1];   // [128,1024]
    const float* cov  = (const float*)d_in[2];   // [6272]
    const float* W_g  = (const float*)d_in[3];   // [4096,4096]
    const float* b_g  = (const float*)d_in[4];   // [4096]
    const float* W_gs = (const float*)d_in[5];   // [4096,1024]
    const float* b_gs = (const float*)d_in[6];   // [1024]
    const float* W_h  = (const float*)d_in[7];   // [1024,1024]
    const float* W_s  = (const float*)d_in[8];   // [1024,1024]
    const float* W_c  = (const float*)d_in[9];   // [1024]
    const float* v    = (const float*)d_in[10];  // [1024]
    float* out = (float*)d_out;                  // [128,1024]

    __half *Xh, *Wgh, *WgsTh, *WcombTh, *WhTh, *WsTh, *sth, *gstarh;
    float *parts, *biascomb, *sproj, *scores;
    cudaGetSymbolAddress((void**)&Xh,       g_Xh);
    cudaGetSymbolAddress((void**)&Wgh,      g_Wgh);
    cudaGetSymbolAddress((void**)&WgsTh,    g_WgsTh);
    cudaGetSymbolAddress((void**)&WcombTh,  g_WcombTh);
    cudaGetSymbolAddress((void**)&WhTh,     g_WhTh);
    cudaGetSymbolAddress((void**)&WsTh,     g_WsTh);
    cudaGetSymbolAddress((void**)&sth,      g_sth);
    cudaGetSymbolAddress((void**)&gstarh,   g_gstarh);
    cudaGetSymbolAddress((void**)&parts,    g_parts);
    cudaGetSymbolAddress((void**)&biascomb, g_biascomb);
    cudaGetSymbolAddress((void**)&sproj,    g_sproj);
    cudaGetSymbolAddress((void**)&scores,   g_scores);

    const int SM4 = GemmDims<4>::SMEM;   // 96KB
    const int SM2 = GemmDims<2>::SMEM;   // 72KB
    cudaFuncSetAttribute(mma_gemm_h,
                         cudaFuncAttributeMaxDynamicSharedMemorySize, SM4);
    cudaFuncSetAttribute(mma_gemm_part,
                         cudaFuncAttributeMaxDynamicSharedMemorySize, SM4);
    cudaFuncSetAttribute(mma_gemm_splitk,
                         cudaFuncAttributeMaxDynamicSharedMemorySize, SM4);
    cudaFuncSetAttribute(epre_scores_gemm,
                         cudaFuncAttributeMaxDynamicSharedMemorySize, SM2);

    // zero biascomb (graph-capturable async memset), then batched prologue
    cudaMemsetAsync(biascomb, 0, H_ * sizeof(float));
    prep_kernel<<<PREP_END, 256>>>(W_gs, WgsTh, W_h, WhTh, W_s, WsTh,
                                   s_t, sth, X, Xh, W_g, Wgh,
                                   b_g, biascomb, scores, sproj);

    // WcombT = fp16(WgsT @ W_g^T)  — single pass, direct fp16 store
    mma_gemm_h<<<dim3(G_ / 128, H_ / 128), 128, SM4>>>(
        WgsTh, Wgh, WcombTh, G_, G_);

    // gstar partials = X @ WcombT^T, split-K x3 (22/22/20 chunks of 64)
    mma_gemm_part<<<dim3(H_ / 128, BN_ / 128, 3), 128, SM4>>>(
        Xh, WcombTh, parts, (size_t)BN_ * H_, H_, G_, 22);
    // gstarh = fp16(p0+p1+p2 + biascomb + b_gs)
    reduce3_bias_kernel<<<(BN_ * H_ / 4) / 256, 256>>>(
        parts, parts + (size_t)BN_ * H_, parts + 2 * (size_t)BN_ * H_,
        biascomb, b_gs, gstarh);

    // s_proj = sth @ WsT^T   (split-K x8, atomic into zeroed buffer)
    mma_gemm_splitk<<<dim3(A_ / 128, 1, 8), 128, SM4>>>(
        sth, WsTh, sproj, B_, A_, H_, H_ / 8);

    // fused: e_pre + tanh + v-dot -> scores
    epre_scores_gemm<<<dim3(A_ / 128, BN_ / 64), 128, SM2>>>(
        gstarh, WhTh, sproj, cov, W_c, v, scores);

    context_kernel<<<B_, 256>>>(scores, gstarh, out);
}

// round 16
// speedup vs baseline: 1.5866x; 1.0080x over previous
#include <cuda_runtime.h>
#include <cuda_fp16.h>
#include <math.h>
#include <stdint.h>

// ===========================================================================
// img_attention via warp-level FP16 mma.sync m16n8k16 (compute_103-safe)
//   c_img = softmax(v . tanh(Wh g* + Ws s + Wc cov)) @ g*
//   g*    = X @ (W_g @ W_gs) + (b_g @ W_gs + b_gs)      [algebraic fold]
// R15: fp16 split-K partials (halved reduce traffic), zero-fills moved to
//      cudaMemsetAsync. Otherwise R14 (which hit its prediction).
// ===========================================================================

#define B_   128
#define N_   49
#define G_   4096
#define H_   1024
#define A_   1024
#define BN_  (B_ * N_)   // 6272

__device__ __half g_Xh[BN_ * G_];        // X fp16
__device__ __half g_Wgh[G_ * G_];        // W_g fp16
__device__ __half g_WgsTh[H_ * G_];      // W_gs^T fp16
__device__ __half g_WcombTh[H_ * G_];    // (W_g@W_gs)^T fp16
__device__ __half g_WhTh[A_ * H_];       // W_h^T fp16
__device__ __half g_WsTh[A_ * H_];       // W_s^T fp16
__device__ __half g_sth[B_ * H_];        // s_t fp16
__device__ __half g_gstarh[BN_ * H_];    // gstar fp16 (epre A + context)
__device__ __half g_parts[3 * BN_ * H_]; // split-K partials (fp16)
__device__ float  g_biascomb[H_];        // b_g @ W_gs (memset to 0)
__device__ float  g_sproj[B_ * A_];      // memset to 0
__device__ float  g_scores[BN_];         // memset to 0

// ---------------------------------------------------------------------------
__device__ __forceinline__ uint32_t smem_u32(const void* p) {
    uint32_t a;
    asm("{ .reg .u64 t; cvta.to.shared.u64 t, %1; cvt.u32.u64 %0, t; }"
        : "=r"(a) : "l"(p));
    return a;
}
__device__ __forceinline__ float tanh_approx(float x) {
    float y;
    asm("tanh.approx.f32 %0, %1;" : "=f"(y) : "f"(x));
    return y;
}
__device__ __forceinline__ void ldsm4(uint32_t* r, uint32_t addr) {
    asm volatile("ldmatrix.sync.aligned.m8n8.x4.shared.b16 {%0,%1,%2,%3}, [%4];"
                 : "=r"(r[0]), "=r"(r[1]), "=r"(r[2]), "=r"(r[3]) : "r"(addr));
}
__device__ __forceinline__ void mma_f16(float* d, const uint32_t* a,
                                        const uint32_t* b) {
    asm volatile(
        "mma.sync.aligned.m16n8k16.row.col.f32.f16.f16.f32 "
        "{%0,%1,%2,%3}, {%4,%5,%6,%7}, {%8,%9}, {%0,%1,%2,%3};"
        : "+f"(d[0]), "+f"(d[1]), "+f"(d[2]), "+f"(d[3])
        : "r"(a[0]), "r"(a[1]), "r"(a[2]), "r"(a[3]), "r"(b[0]), "r"(b[1]));
}
#define CPA(dst, src) \
    asm volatile("cp.async.cg.shared.global [%0], [%1], 16;" \
                 :: "r"(dst), "l"(src) : "memory")
#define CPCOMMIT() asm volatile("cp.async.commit_group;" ::: "memory")
#define CPWAIT1()  asm volatile("cp.async.wait_group 1;" ::: "memory")
#define CPWAIT0()  asm volatile("cp.async.wait_group 0;" ::: "memory")

// ---------------------------------------------------------------------------
// GEMM core (fp16). FM = A-fragments per warp (M-tile = FM*32).
// BK = 64 fp16 = 128B rows. 3-stage cp.async ring, frag double-buffer.
// ---------------------------------------------------------------------------
template <int FM>
struct GemmDims {
    static const int ABYTES = FM * 32 * 128;
    static const int STAGE  = ABYTES + 16384;
    static const int SMEM   = 3 * STAGE;
    static const int OCC    = (FM == 2) ? 3 : 2;
};

#define GEMM_PROLOG(FM)                                                       \
    extern __shared__ char smem[];                                            \
    const uint32_t sb = smem_u32(smem);                                       \
    const int tid = threadIdx.x;                                              \
    const int lane = tid & 31;                                                \
    const int wid = tid >> 5;                                                 \
    const int wr = wid >> 1;                                                  \
    const int wc = wid & 1;                                                   \
    const int srow = tid >> 3, sc4 = tid & 7;                                 \
    const uint32_t soff0 = (uint32_t)srow * 128 + ((sc4 ^ (srow & 7)) << 4);  \
    const int aRow = wr * (FM * 16) + ((lane >> 3) & 1) * 8 + (lane & 7);     \
    const int cbA = lane >> 4;                                                \
    const uint32_t aBase = (uint32_t)aRow * 128;                              \
    const int rmA = aRow & 7;                                                 \
    const int bRow = wc * 64 + (lane >> 4) * 8 + (lane & 7);                  \
    const int cbB = (lane >> 3) & 1;                                          \
    const uint32_t bBase = (uint32_t)bRow * 128;                              \
    const int rmB = bRow & 7;                                                 \
    float acc[FM][8][4];                                                      \
    _Pragma("unroll") for (int i = 0; i < FM; i++)                            \
        _Pragma("unroll") for (int j = 0; j < 8; j++)                         \
            _Pragma("unroll") for (int q = 0; q < 4; q++) acc[i][j][q] = 0.f;

template <int FM>
__device__ __forceinline__ void gemm_core(
    const __half* __restrict__ pA0, const __half* __restrict__ pB0,
    size_t strideJ, int nch, uint32_t sb, uint32_t soff0,
    uint32_t aBase, int rmA, int cbA,
    uint32_t bBase, int rmB, int cbB,
    float (&acc)[FM][8][4])
{
    const int ABYTES = GemmDims<FM>::ABYTES;
    const int STAGE  = GemmDims<FM>::STAGE;
    const int JA = FM * 2;

    auto issue = [&](uint32_t sbase, int k0) {
        #pragma unroll
        for (int j = 0; j < JA; j++)
            CPA(sbase + soff0 + j * 2048, pA0 + k0 + j * strideJ);
        #pragma unroll
        for (int j = 0; j < 8; j++)
            CPA(sbase + ABYTES + soff0 + j * 2048, pB0 + k0 + j * strideJ);
        CPCOMMIT();
    };

    uint32_t afr[2][FM][4], bfr[2][8][2];

    auto ldA = [&](uint32_t As, int kc, int buf) {
        #pragma unroll
        for (int fm = 0; fm < FM; fm++)
            ldsm4(afr[buf][fm],
                  As + fm * 2048 + aBase + ((((kc * 2) + cbA) ^ rmA) << 4));
    };
    auto ldB = [&](uint32_t Bs, int kc, int buf) {
        #pragma unroll
        for (int p = 0; p < 4; p++) {
            uint32_t t4[4];
            ldsm4(t4, Bs + p * 2048 + bBase + ((((kc * 2) + cbB) ^ rmB) << 4));
            bfr[buf][2*p][0]   = t4[0]; bfr[buf][2*p][1]   = t4[1];
            bfr[buf][2*p+1][0] = t4[2]; bfr[buf][2*p+1][1] = t4[3];
        }
    };

    issue(sb, 0);
    issue(sb + STAGE, 64);
    int cs = 0, is = 2;
    for (int c = 0; c < nch; c++) {
        if (c == nch - 1) { CPWAIT0(); } else { CPWAIT1(); }
        __syncthreads();
        if (c + 2 < nch) {
            issue(sb + is * STAGE, (c + 2) * 64);
            is = (is == 2) ? 0 : is + 1;
        }
        const uint32_t As = sb + cs * STAGE;
        const uint32_t Bs = As + ABYTES;
        ldA(As, 0, 0);
        ldB(Bs, 0, 0);
        #pragma unroll
        for (int kc = 0; kc < 4; kc++) {
            const int cur = kc & 1;
            if (kc < 3) {
                ldA(As, kc + 1, cur ^ 1);
                ldB(Bs, kc + 1, cur ^ 1);
            }
            #pragma unroll
            for (int fm = 0; fm < FM; fm++)
                #pragma unroll
                for (int fn = 0; fn < 8; fn++)
                    mma_f16(acc[fm][fn], afr[cur][fm], bfr[cur][fn]);
        }
        cs = (cs == 2) ? 0 : cs + 1;
    }
}

// ---------------------------------------------------------------------------
// Full-K GEMM with direct fp16 store (Wcomb): Ch = fp16(A @ Bt^T).
// ---------------------------------------------------------------------------
__global__ __launch_bounds__(128, 2)
void mma_gemm_h(const __half* __restrict__ A, const __half* __restrict__ Bt,
                __half* __restrict__ Ch, int Nn, int K)
{
    const int bm = blockIdx.y * 128;
    const int bn = blockIdx.x * 128;
    GEMM_PROLOG(4);
    const __half* pA0 = A  + (size_t)(bm + srow) * K + sc4 * 8;
    const __half* pB0 = Bt + (size_t)(bn + srow) * K + sc4 * 8;
    const size_t strideJ = (size_t)16 * K;
    gemm_core<4>(pA0, pB0, strideJ, K >> 6, sb, soff0,
                 aBase, rmA, cbA, bBase, rmB, cbB, acc);

    const int gid = lane >> 2, tig = lane & 3;
    #pragma unroll
    for (int fm = 0; fm < 4; fm++) {
        const int row = bm + wr * 64 + fm * 16 + gid;
        #pragma unroll
        for (int fn = 0; fn < 8; fn++) {
            const int col = bn + wc * 64 + fn * 8 + tig * 2;
            *(__half2*)(Ch + (size_t)row * Nn + col) =
                __floats2half2_rn(acc[fm][fn][0], acc[fm][fn][1]);
            *(__half2*)(Ch + (size_t)(row + 8) * Nn + col) =
                __floats2half2_rn(acc[fm][fn][2], acc[fm][fn][3]);
        }
    }
}

// ---------------------------------------------------------------------------
// Split-K partial GEMM (gstar): Cpart[z] = fp16(A @ Bt^T over K slice z).
// ---------------------------------------------------------------------------
__global__ __launch_bounds__(128, 2)
void mma_gemm_part(const __half* __restrict__ A, const __half* __restrict__ Bt,
                   __half* __restrict__ Cparts, size_t zstride,
                   int Nn, int K, int nchA)
{
    const int bm = blockIdx.y * 128;
    const int bn = blockIdx.x * 128;
    const int z  = blockIdx.z;
    const int kbase = z * nchA * 64;
    int nch = (K >> 6) - z * nchA;
    if (nch > nchA) nch = nchA;
    __half* C = Cparts + (size_t)z * zstride;

    GEMM_PROLOG(4);
    const __half* pA0 = A  + (size_t)(bm + srow) * K + kbase + sc4 * 8;
    const __half* pB0 = Bt + (size_t)(bn + srow) * K + kbase + sc4 * 8;
    const size_t strideJ = (size_t)16 * K;
    gemm_core<4>(pA0, pB0, strideJ, nch, sb, soff0,
                 aBase, rmA, cbA, bBase, rmB, cbB, acc);

    const int gid = lane >> 2, tig = lane & 3;
    #pragma unroll
    for (int fm = 0; fm < 4; fm++) {
        const int row = bm + wr * 64 + fm * 16 + gid;
        #pragma unroll
        for (int fn = 0; fn < 8; fn++) {
            const int col = bn + wc * 64 + fn * 8 + tig * 2;
            *(__half2*)(C + (size_t)row * Nn + col) =
                __floats2half2_rn(acc[fm][fn][0], acc[fm][fn][1]);
            *(__half2*)(C + (size_t)(row + 8) * Nn + col) =
                __floats2half2_rn(acc[fm][fn][2], acc[fm][fn][3]);
        }
    }
}

// ---------------------------------------------------------------------------
// Split-K GEMM for skinny M=128 (sproj): atomics into zeroed C.
// ---------------------------------------------------------------------------
__global__ __launch_bounds__(128, 2)
void mma_gemm_splitk(const __half* __restrict__ A, const __half* __restrict__ Bt,
                     float* __restrict__ C, int M, int Nn, int K, int klen)
{
    const int bm = blockIdx.y * 128;
    const int bn = blockIdx.x * 128;
    const int kbase = blockIdx.z * klen;
    GEMM_PROLOG(4);
    const __half* pA0 = A  + (size_t)(bm + srow) * K + kbase + sc4 * 8;
    const __half* pB0 = Bt + (size_t)(bn + srow) * K + kbase + sc4 * 8;
    const size_t strideJ = (size_t)16 * K;
    gemm_core<4>(pA0, pB0, strideJ, klen >> 6, sb, soff0,
                 aBase, rmA, cbA, bBase, rmB, cbB, acc);

    const int gid = lane >> 2, tig = lane & 3;
    #pragma unroll
    for (int fm = 0; fm < 4; fm++) {
        const int row = bm + wr * 64 + fm * 16 + gid;
        #pragma unroll
        for (int fn = 0; fn < 8; fn++) {
            const int col = bn + wc * 64 + fn * 8 + tig * 2;
            atomicAdd(C + (size_t)row * Nn + col,       acc[fm][fn][0]);
            atomicAdd(C + (size_t)row * Nn + col + 1,   acc[fm][fn][1]);
            atomicAdd(C + (size_t)(row+8) * Nn + col,   acc[fm][fn][2]);
            atomicAdd(C + (size_t)(row+8) * Nn + col+1, acc[fm][fn][3]);
        }
    }
}

// ---------------------------------------------------------------------------
// Fused e_pre GEMM + scores epilogue (FM=2 tiles, 3 CTAs/SM).
// ---------------------------------------------------------------------------
__global__ __launch_bounds__(128, 3)
void epre_scores_gemm(const __half* __restrict__ A, const __half* __restrict__ Bt,
                      const float* __restrict__ sproj,
                      const float* __restrict__ cov,
                      const float* __restrict__ Wc,
                      const float* __restrict__ v,
                      float* __restrict__ scores)
{
    const int bm = blockIdx.y * 64;
    const int bn = blockIdx.x * 128;
    GEMM_PROLOG(2);
    const __half* pA0 = A  + (size_t)(bm + srow) * H_ + sc4 * 8;
    const __half* pB0 = Bt + (size_t)(bn + srow) * H_ + sc4 * 8;
    const size_t strideJ = (size_t)16 * H_;
    gemm_core<2>(pA0, pB0, strideJ, H_ >> 6, sb, soff0,
                 aBase, rmA, cbA, bBase, rmB, cbB, acc);

    const int gid = lane >> 2, tig = lane & 3;
    float vv[16], wcv[16];
    #pragma unroll
    for (int fn = 0; fn < 8; fn++) {
        const int col = bn + wc * 64 + fn * 8 + tig * 2;
        vv[2*fn]   = v[col];      vv[2*fn+1]  = v[col + 1];
        wcv[2*fn]  = Wc[col];     wcv[2*fn+1] = Wc[col + 1];
    }
    #pragma unroll
    for (int fm = 0; fm < 2; fm++) {
        const int r0 = bm + wr * 32 + fm * 16 + gid;
        const int r1 = r0 + 8;
        const int b0i = r0 / N_, b1i = r1 / N_;
        const float c0 = cov[r0], c1 = cov[r1];
        const float* sp0 = sproj + (size_t)b0i * A_;
        const float* sp1 = sproj + (size_t)b1i * A_;
        float p0 = 0.f, p1 = 0.f;
        #pragma unroll
        for (int fn = 0; fn < 8; fn++) {
            const int col = bn + wc * 64 + fn * 8 + tig * 2;
            p0 += vv[2*fn]   * tanh_approx(acc[fm][fn][0] + sp0[col]     + c0 * wcv[2*fn]);
            p0 += vv[2*fn+1] * tanh_approx(acc[fm][fn][1] + sp0[col + 1] + c0 * wcv[2*fn+1]);
            p1 += vv[2*fn]   * tanh_approx(acc[fm][fn][2] + sp1[col]     + c1 * wcv[2*fn]);
            p1 += vv[2*fn+1] * tanh_approx(acc[fm][fn][3] + sp1[col + 1] + c1 * wcv[2*fn+1]);
        }
        p0 += __shfl_xor_sync(0xffffffffu, p0, 1);
        p0 += __shfl_xor_sync(0xffffffffu, p0, 2);
        p1 += __shfl_xor_sync(0xffffffffu, p1, 1);
        p1 += __shfl_xor_sync(0xffffffffu, p1, 2);
        if (tig == 0) {
            atomicAdd(scores + r0, p0);
            atomicAdd(scores + r1, p1);
        }
    }
}

// ---------------------------------------------------------------------------
// gstarh = fp16(p0+p1+p2 + biascomb[col] + b_gs[col])  (fp16 partials)
// ---------------------------------------------------------------------------
__global__ __launch_bounds__(256) void reduce3_bias_kernel(
    const __half* __restrict__ p0, const __half* __restrict__ p1,
    const __half* __restrict__ p2, const float* __restrict__ biascomb,
    const float* __restrict__ b_gs, __half* __restrict__ outh)
{
    const size_t i = ((size_t)blockIdx.x * 256 + threadIdx.x) * 4;
    const int col = (int)(i & (H_ - 1));
    const __half2* a2 = (const __half2*)(p0 + i);
    const __half2* b2 = (const __half2*)(p1 + i);
    const __half2* c2 = (const __half2*)(p2 + i);
    float2 a0 = __half22float2(a2[0]), a1 = __half22float2(a2[1]);
    float2 b0 = __half22float2(b2[0]), b1 = __half22float2(b2[1]);
    float2 c0 = __half22float2(c2[0]), c1 = __half22float2(c2[1]);
    float4 d = *(const float4*)(biascomb + col);
    float4 e = *(const float4*)(b_gs + col);
    *(__half2*)(outh + i) =
        __floats2half2_rn(a0.x + b0.x + c0.x + d.x + e.x,
                          a0.y + b0.y + c0.y + d.y + e.y);
    *(__half2*)(outh + i + 2) =
        __floats2half2_rn(a1.x + b1.x + c1.x + d.z + e.z,
                          a1.y + b1.y + c1.y + d.w + e.w);
}

// ---------------------------------------------------------------------------
// Batched prologue: fp16 transposes/conversions + bias_acc.
// biascomb must be zeroed (cudaMemsetAsync) before this kernel.
// ---------------------------------------------------------------------------
#define PREP_T1 4096                        // W_gs transpose
#define PREP_T2 (PREP_T1 + 1024)            // W_h transpose
#define PREP_T3 (PREP_T2 + 1024)            // W_s transpose
#define PREP_CS (PREP_T3 + 64)              // s_t -> fp16
#define PREP_CX (PREP_CS + 12544)           // X -> fp16
#define PREP_CW (PREP_CX + 8192)            // W_g -> fp16
#define PREP_BA (PREP_CW + 64)              // bias_acc
#define PREP_END PREP_BA

__device__ __forceinline__ void conv8(const float* __restrict__ in,
                                      __half* __restrict__ out, size_t i8) {
    float4 a = *(const float4*)(in + i8);
    float4 b = *(const float4*)(in + i8 + 4);
    __half2 h[4];
    h[0] = __floats2half2_rn(a.x, a.y);
    h[1] = __floats2half2_rn(a.z, a.w);
    h[2] = __floats2half2_rn(b.x, b.y);
    h[3] = __floats2half2_rn(b.z, b.w);
    *(uint4*)(out + i8) = *(const uint4*)h;
}

__device__ __forceinline__ void do_transpose32h(
    const float* __restrict__ in, __half* __restrict__ out,
    int R, int C, int tx, int ty)
{
    __shared__ float t[32][33];
    const int c0 = tx * 32, r0 = ty * 32;
    const int x = threadIdx.x & 31, y = (threadIdx.x >> 5);
    #pragma unroll
    for (int j = 0; j < 32; j += 8)
        t[y + j][x] = in[(size_t)(r0 + y + j) * C + c0 + x];
    __syncthreads();
    #pragma unroll
    for (int j = 0; j < 32; j += 8)
        out[(size_t)(c0 + y + j) * R + r0 + x] = __float2half_rn(t[x][y + j]);
}

__global__ __launch_bounds__(256) void prep_kernel(
    const float* __restrict__ W_gs, __half* __restrict__ WgsTh,
    const float* __restrict__ W_h,  __half* __restrict__ WhTh,
    const float* __restrict__ W_s,  __half* __restrict__ WsTh,
    const float* __restrict__ s_t,  __half* __restrict__ sth,
    const float* __restrict__ X,    __half* __restrict__ Xh,
    const float* __restrict__ W_g,  __half* __restrict__ Wgh,
    const float* __restrict__ b_g,  float* __restrict__ biascomb)
{
    const int bid = blockIdx.x;
    if (bid < PREP_T1) {
        do_transpose32h(W_gs, WgsTh, G_, H_, bid & 31, bid >> 5);
    } else if (bid < PREP_T2) {
        const int b = bid - PREP_T1;
        do_transpose32h(W_h, WhTh, H_, A_, b & 31, b >> 5);
    } else if (bid < PREP_T3) {
        const int b = bid - PREP_T2;
        do_transpose32h(W_s, WsTh, H_, A_, b & 31, b >> 5);
    } else if (bid < PREP_CS) {
        conv8(s_t, sth, ((size_t)(bid - PREP_T3) * 256 + threadIdx.x) * 8);
    } else if (bid < PREP_CX) {
        conv8(X, Xh, ((size_t)(bid - PREP_CS) * 256 + threadIdx.x) * 8);
    } else if (bid < PREP_CW) {
        conv8(W_g, Wgh, ((size_t)(bid - PREP_CX) * 256 + threadIdx.x) * 8);
    } else {
        const int b = bid - PREP_CW;        // 0..63
        const int h = (b & 3) * 256 + threadIdx.x;
        const int k0 = (b >> 2) * 256;
        float acc = 0.f;
        #pragma unroll 4
        for (int k = k0; k < k0 + 256; k++)
            acc += b_g[k] * W_gs[(size_t)k * H_ + h];
        atomicAdd(&biascomb[h], acc);
    }
}

// softmax over N=49 + context c[b,h] = sum_n alpha[n] * gstarh[b,n,h]
__global__ __launch_bounds__(256) void context_kernel(
    const float* __restrict__ scores, const __half* __restrict__ gstarh,
    float* __restrict__ out)
{
    const int b = blockIdx.x;
    __shared__ float alpha[N_];
    const int tid = threadIdx.x;

    if (tid == 0) {
        float m = -1e30f;
        #pragma unroll
        for (int n = 0; n < N_; n++) m = fmaxf(m, scores[b * N_ + n]);
        float s = 0.f;
        #pragma unroll
        for (int n = 0; n < N_; n++) {
            float e = expf(scores[b * N_ + n] - m);
            alpha[n] = e;
            s += e;
        }
        float inv = 1.f / s;
        #pragma unroll
        for (int n = 0; n < N_; n++) alpha[n] *= inv;
    }
    __syncthreads();

    const __half* gb = gstarh + (size_t)b * N_ * H_;
    for (int h = tid; h < H_; h += 256) {
        float acc = 0.f;
        #pragma unroll
        for (int n = 0; n < N_; n++)
            acc += alpha[n] * __half2float(gb[(size_t)n * H_ + h]);
        out[(size_t)b * H_ + h] = acc;
    }
}

// ---------------------------------------------------------------------------
extern "C" void kernel_launch(void* const* d_in, const int* in_sizes, int n_in,
                              void* d_out, int out_size) {
    const float* X    = (const float*)d_in[0];   // [6272,4096]
    const float* s_t  = (const float*)d_in[1];   // [128,1024]
    const float* cov  = (const float*)d_in[2];   // [6272]
    const float* W_g  = (const float*)d_in[3];   // [4096,4096]
    const float* b_g  = (const float*)d_in[4];   // [4096]
    const float* W_gs = (const float*)d_in[5];   // [4096,1024]
    const float* b_gs = (const float*)d_in[6];   // [1024]
    const float* W_h  = (const float*)d_in[7];   // [1024,1024]
    const float* W_s  = (const float*)d_in[8];   // [1024,1024]
    const float* W_c  = (const float*)d_in[9];   // [1024]
    const float* v    = (const float*)d_in[10];  // [1024]
    float* out = (float*)d_out;                  // [128,1024]

    __half *Xh, *Wgh, *WgsTh, *WcombTh, *WhTh, *WsTh, *sth, *gstarh, *parts;
    float *biascomb, *sproj, *scores;
    cudaGetSymbolAddress((void**)&Xh,       g_Xh);
    cudaGetSymbolAddress((void**)&Wgh,      g_Wgh);
    cudaGetSymbolAddress((void**)&WgsTh,    g_WgsTh);
    cudaGetSymbolAddress((void**)&WcombTh,  g_WcombTh);
    cudaGetSymbolAddress((void**)&WhTh,     g_WhTh);
    cudaGetSymbolAddress((void**)&WsTh,     g_WsTh);
    cudaGetSymbolAddress((void**)&sth,      g_sth);
    cudaGetSymbolAddress((void**)&gstarh,   g_gstarh);
    cudaGetSymbolAddress((void**)&parts,    g_parts);
    cudaGetSymbolAddress((void**)&biascomb, g_biascomb);
    cudaGetSymbolAddress((void**)&sproj,    g_sproj);
    cudaGetSymbolAddress((void**)&scores,   g_scores);

    const int SM4 = GemmDims<4>::SMEM;   // 96KB
    const int SM2 = GemmDims<2>::SMEM;   // 72KB
    cudaFuncSetAttribute(mma_gemm_h,
                         cudaFuncAttributeMaxDynamicSharedMemorySize, SM4);
    cudaFuncSetAttribute(mma_gemm_part,
                         cudaFuncAttributeMaxDynamicSharedMemorySize, SM4);
    cudaFuncSetAttribute(mma_gemm_splitk,
                         cudaFuncAttributeMaxDynamicSharedMemorySize, SM4);
    cudaFuncSetAttribute(epre_scores_gemm,
                         cudaFuncAttributeMaxDynamicSharedMemorySize, SM2);

    // graph-capturable async zero-fills
    cudaMemsetAsync(biascomb, 0, H_ * sizeof(float));
    cudaMemsetAsync(scores,   0, BN_ * sizeof(float));
    cudaMemsetAsync(sproj,    0, (size_t)B_ * A_ * sizeof(float));

    // batched prologue: fp16 transposes + conversions + bias_acc
    prep_kernel<<<PREP_END, 256>>>(W_gs, WgsTh, W_h, WhTh, W_s, WsTh,
                                   s_t, sth, X, Xh, W_g, Wgh, b_g, biascomb);

    // WcombT = fp16(WgsT @ W_g^T)  — single pass, direct fp16 store
    mma_gemm_h<<<dim3(G_ / 128, H_ / 128), 128, SM4>>>(
        WgsTh, Wgh, WcombTh, G_, G_);

    // gstar partials = fp16(X @ WcombT^T), split-K x3 (22/22/20 chunks)
    mma_gemm_part<<<dim3(H_ / 128, BN_ / 128, 3), 128, SM4>>>(
        Xh, WcombTh, parts, (size_t)BN_ * H_, H_, G_, 22);
    // gstarh = fp16(p0+p1+p2 + biascomb + b_gs)
    reduce3_bias_kernel<<<(BN_ * H_ / 4) / 256, 256>>>(
        parts, parts + (size_t)BN_ * H_, parts + 2 * (size_t)BN_ * H_,
        biascomb, b_gs, gstarh);

    // s_proj = sth @ WsT^T   (split-K x8, atomic into zeroed buffer)
    mma_gemm_splitk<<<dim3(A_ / 128, 1, 8), 128, SM4>>>(
        sth, WsTh, sproj, B_, A_, H_, H_ / 8);

    // fused: e_pre + tanh + v-dot -> scores
    epre_scores_gemm<<<dim3(A_ / 128, BN_ / 64), 128, SM2>>>(
        gstarh, WhTh, sproj, cov, W_c, v, scores);

    context_kernel<<<B_, 256>>>(scores, gstarh, out);
}